// round 1
// baseline (speedup 1.0000x reference)
#include <cuda_runtime.h>
#include <math.h>

// ---------------- problem constants ----------------
static constexpr int cB = 2, cS = 512, cD = 768, cH = 12, cDH = 64;
static constexpr int cEA = 4, cEF = 8, cDFF = 3072, cN = 1024, cCAP = 160;

// ---------------- scratch (device globals; no allocation allowed) ----------
__device__ float g_h1[cN * cD];
__device__ float g_q[cN * cD];
__device__ float g_k[cN * cD];
__device__ float g_gate[cN * cH * cEA];
__device__ float g_p[(size_t)cB * cH * cS * cS];          // scores -> probs
__device__ int   g_aidx[cN * cH];
__device__ float g_hard[cH * cEA];
__device__ float g_vproj[cH * cB * cS * cDH];             // (h,b,s,d)
__device__ float g_attnout[cH * cB * cS * cDH];           // (h,b,t,d)
__device__ float g_x1[cN * cD];
__device__ float g_h2[cN * cD];
__device__ float g_gl[cN * cEF];
__device__ int   g_top_e[cN * 2];
__device__ float g_top_p[cN * 2];
__device__ int   g_pos[cN * 2];
__device__ float g_w[cN * 2];
__device__ float g_buf[cEF * cCAP * cD];
__device__ float g_hmid[(size_t)cEF * cCAP * cDFF];
__device__ float g_ybuf[cEF * cCAP * cD];

// ---------------- small kernels ----------------
__global__ void zero_kernel() {
    int t = threadIdx.x;
    if (t < cH * cEA) g_hard[t] = 0.f;
}

__global__ void ln_kernel(const float* __restrict__ in, const float* __restrict__ gam,
                          const float* __restrict__ bet, float* __restrict__ out) {
    int row = blockIdx.x;
    const float* r = in + (size_t)row * cD;
    __shared__ float red[256];
    int t = threadIdx.x;
    float s = 0.f;
    for (int i = t; i < cD; i += 256) s += r[i];
    red[t] = s; __syncthreads();
    for (int o = 128; o > 0; o >>= 1) { if (t < o) red[t] += red[t + o]; __syncthreads(); }
    float mu = red[0] / cD;
    __syncthreads();
    float s2 = 0.f;
    for (int i = t; i < cD; i += 256) { float d = r[i] - mu; s2 += d * d; }
    red[t] = s2; __syncthreads();
    for (int o = 128; o > 0; o >>= 1) { if (t < o) red[t] += red[t + o]; __syncthreads(); }
    float inv = rsqrtf(red[0] / cD + 1e-5f);
    for (int i = t; i < cD; i += 256)
        out[(size_t)row * cD + i] = (r[i] - mu) * inv * gam[i] + bet[i];
}

// ---------------- generic tiled GEMMs (64x64 tile, BK=16, 4x4/thread) ------
// C = A(MxK) * B(KxN)
__global__ __launch_bounds__(256) void gemm_nn(
    const float* __restrict__ A, const float* __restrict__ Bm, float* __restrict__ C,
    int M, int Nc, int Kd, int lda, int ldb, int ldc,
    int zdiv, long sA1, long sA2, long sB1, long sB2, long sC1, long sC2, int relu) {
    long zb = blockIdx.z / zdiv, zi = blockIdx.z % zdiv;
    A += zb * sA1 + zi * sA2; Bm += zb * sB1 + zi * sB2; C += zb * sC1 + zi * sC2;
    __shared__ float As[16][65];
    __shared__ float Bs[16][65];
    int tid = threadIdx.x;
    int tx = tid & 15, ty = tid >> 4;
    int m0 = blockIdx.y * 64, n0 = blockIdx.x * 64;
    float acc[4][4] = {};
    for (int k0 = 0; k0 < Kd; k0 += 16) {
#pragma unroll
        for (int r = 0; r < 4; r++) {
            int m = (tid >> 4) + r * 16, kk = tid & 15;
            As[kk][m] = (m0 + m < M) ? A[(long)(m0 + m) * lda + k0 + kk] : 0.f;
            int nn = tid & 63, kb = (tid >> 6) + r * 4;
            Bs[kb][nn] = (n0 + nn < Nc) ? Bm[(long)(k0 + kb) * ldb + n0 + nn] : 0.f;
        }
        __syncthreads();
#pragma unroll
        for (int kk = 0; kk < 16; kk++) {
            float a[4], b[4];
#pragma unroll
            for (int i = 0; i < 4; i++) a[i] = As[kk][ty * 4 + i];
#pragma unroll
            for (int j = 0; j < 4; j++) b[j] = Bs[kk][tx * 4 + j];
#pragma unroll
            for (int i = 0; i < 4; i++)
#pragma unroll
                for (int j = 0; j < 4; j++) acc[i][j] += a[i] * b[j];
        }
        __syncthreads();
    }
#pragma unroll
    for (int i = 0; i < 4; i++)
#pragma unroll
        for (int j = 0; j < 4; j++) {
            int m = m0 + ty * 4 + i, n = n0 + tx * 4 + j;
            if (m < M && n < Nc) {
                float v = acc[i][j];
                if (relu) v = fmaxf(v, 0.f);
                C[(long)m * ldc + n] = v;
            }
        }
}

// C = A(MxK) * B(NxK)^T
__global__ __launch_bounds__(256) void gemm_nt(
    const float* __restrict__ A, const float* __restrict__ Bm, float* __restrict__ C,
    int M, int Nc, int Kd, int lda, int ldb, int ldc,
    int zdiv, long sA1, long sA2, long sB1, long sB2, long sC1, long sC2) {
    long zb = blockIdx.z / zdiv, zi = blockIdx.z % zdiv;
    A += zb * sA1 + zi * sA2; Bm += zb * sB1 + zi * sB2; C += zb * sC1 + zi * sC2;
    __shared__ float As[16][65];
    __shared__ float Bs[16][65];
    int tid = threadIdx.x;
    int tx = tid & 15, ty = tid >> 4;
    int m0 = blockIdx.y * 64, n0 = blockIdx.x * 64;
    float acc[4][4] = {};
    for (int k0 = 0; k0 < Kd; k0 += 16) {
#pragma unroll
        for (int r = 0; r < 4; r++) {
            int m = (tid >> 4) + r * 16, kk = tid & 15;
            As[kk][m] = (m0 + m < M) ? A[(long)(m0 + m) * lda + k0 + kk] : 0.f;
            Bs[kk][m] = (n0 + m < Nc) ? Bm[(long)(n0 + m) * ldb + k0 + kk] : 0.f;
        }
        __syncthreads();
#pragma unroll
        for (int kk = 0; kk < 16; kk++) {
            float a[4], b[4];
#pragma unroll
            for (int i = 0; i < 4; i++) a[i] = As[kk][ty * 4 + i];
#pragma unroll
            for (int j = 0; j < 4; j++) b[j] = Bs[kk][tx * 4 + j];
#pragma unroll
            for (int i = 0; i < 4; i++)
#pragma unroll
                for (int j = 0; j < 4; j++) acc[i][j] += a[i] * b[j];
        }
        __syncthreads();
    }
#pragma unroll
    for (int i = 0; i < 4; i++)
#pragma unroll
        for (int j = 0; j < 4; j++) {
            int m = m0 + ty * 4 + i, n = n0 + tx * 4 + j;
            if (m < M && n < Nc) C[(long)m * ldc + n] = acc[i][j];
        }
}

// C = A(KxM)^T * B(KxN)
__global__ __launch_bounds__(256) void gemm_tn(
    const float* __restrict__ A, const float* __restrict__ Bm, float* __restrict__ C,
    int M, int Nc, int Kd, int lda, int ldb, int ldc,
    int zdiv, long sA1, long sA2, long sB1, long sB2, long sC1, long sC2) {
    long zb = blockIdx.z / zdiv, zi = blockIdx.z % zdiv;
    A += zb * sA1 + zi * sA2; Bm += zb * sB1 + zi * sB2; C += zb * sC1 + zi * sC2;
    __shared__ float As[16][65];
    __shared__ float Bs[16][65];
    int tid = threadIdx.x;
    int tx = tid & 15, ty = tid >> 4;
    int m0 = blockIdx.y * 64, n0 = blockIdx.x * 64;
    float acc[4][4] = {};
    for (int k0 = 0; k0 < Kd; k0 += 16) {
#pragma unroll
        for (int r = 0; r < 4; r++) {
            int c = tid & 63, kk = (tid >> 6) + r * 4;
            As[kk][c] = (m0 + c < M) ? A[(long)(k0 + kk) * lda + m0 + c] : 0.f;
            Bs[kk][c] = (n0 + c < Nc) ? Bm[(long)(k0 + kk) * ldb + n0 + c] : 0.f;
        }
        __syncthreads();
#pragma unroll
        for (int kk = 0; kk < 16; kk++) {
            float a[4], b[4];
#pragma unroll
            for (int i = 0; i < 4; i++) a[i] = As[kk][ty * 4 + i];
#pragma unroll
            for (int j = 0; j < 4; j++) b[j] = Bs[kk][tx * 4 + j];
#pragma unroll
            for (int i = 0; i < 4; i++)
#pragma unroll
                for (int j = 0; j < 4; j++) acc[i][j] += a[i] * b[j];
        }
        __syncthreads();
    }
#pragma unroll
    for (int i = 0; i < 4; i++)
#pragma unroll
        for (int j = 0; j < 4; j++) {
            int m = m0 + ty * 4 + i, n = n0 + tx * 4 + j;
            if (m < M && n < Nc) C[(long)m * ldc + n] = acc[i][j];
        }
}

// ---------------- attention pieces ----------------
__global__ void softmax_kernel(const float* __restrict__ mask) {
    long rid = blockIdx.x;           // (b*H + h)*S + s
    int s = (int)(rid % cS);
    float* row = g_p + rid * cS;
    int t = threadIdx.x;
    __shared__ float red[256];
    float v0 = row[t] * 0.125f + mask[(long)s * cS + t];
    float v1 = row[t + 256] * 0.125f + mask[(long)s * cS + t + 256];
    float m = fmaxf(v0, v1);
    red[t] = m; __syncthreads();
    for (int o = 128; o > 0; o >>= 1) { if (t < o) red[t] = fmaxf(red[t], red[t + o]); __syncthreads(); }
    float rowmax = red[0];
    __syncthreads();
    float e0 = expf(v0 - rowmax), e1 = expf(v1 - rowmax);
    red[t] = e0 + e1; __syncthreads();
    for (int o = 128; o > 0; o >>= 1) { if (t < o) red[t] += red[t + o]; __syncthreads(); }
    float inv = 1.f / red[0];
    row[t] = e0 * inv;
    row[t + 256] = e1 * inv;
}

__global__ void argmax_kernel() {
    int n = blockIdx.x, h = threadIdx.x;
    if (h >= cH) return;
    const float* g4 = g_gate + (long)n * (cH * cEA) + h * cEA;
    int bi = 0; float bv = g4[0];
#pragma unroll
    for (int ea = 1; ea < cEA; ea++) if (g4[ea] > bv) { bv = g4[ea]; bi = ea; }
    g_aidx[n * cH + h] = bi;
    atomicAdd(&g_hard[h * cEA + bi], 1.f);
}

__global__ void vproj_kernel(const float* __restrict__ Wv) {
    int n = blockIdx.x, h = blockIdx.y, e = threadIdx.x;
    __shared__ float xs[64];
    xs[e] = g_h1[(long)n * cD + h * cDH + e];
    __syncthreads();
    int ei = g_aidx[n * cH + h];
    const float* Wp = Wv + ((long)(h * cEA + ei) * cDH) * cDH;
    float acc = 0.f;
#pragma unroll 8
    for (int d = 0; d < cDH; d++) acc += xs[d] * Wp[d * cDH + e];
    int b = n >> 9, s = n & 511;
    g_vproj[(((long)(h * cB + b) * cS) + s) * cDH + e] = acc;
}

__global__ void oproj_kernel(const float* __restrict__ Wo, const float* __restrict__ x) {
    int n = blockIdx.x, h = blockIdx.y, e = threadIdx.x;
    int b = n >> 9, s = n & 511;
    __shared__ float xs[64];
    xs[e] = g_attnout[(((long)(h * cB + b) * cS) + s) * cDH + e];
    __syncthreads();
    int ei = g_aidx[n * cH + h];
    const float* Wp = Wo + ((long)(h * cEA + ei) * cDH) * cDH;
    float acc = 0.f;
#pragma unroll 8
    for (int d = 0; d < cDH; d++) acc += xs[d] * Wp[d * cDH + e];
    g_x1[(long)n * cD + h * cDH + e] = x[(long)n * cD + h * cDH + e] + acc;
}

// ---------------- MoE FFN pieces ----------------
__global__ void gateff_kernel(const float* __restrict__ gate_w) {
    int n = blockIdx.x;
    int w = threadIdx.x >> 5, lane = threadIdx.x & 31;
    float acc = 0.f;
    for (int d = lane; d < cD; d += 32)
        acc += g_h2[(long)n * cD + d] * gate_w[(long)d * cEF + w];
#pragma unroll
    for (int o = 16; o > 0; o >>= 1) acc += __shfl_down_sync(0xffffffffu, acc, o);
    if (lane == 0) g_gl[n * cEF + w] = acc;
}

__global__ void topk_kernel() {
    int n = blockIdx.x * blockDim.x + threadIdx.x;
    if (n >= cN) return;
    float v[cEF];
#pragma unroll
    for (int j = 0; j < cEF; j++) v[j] = g_gl[n * cEF + j];
    int i1 = 0; float b1 = v[0];
#pragma unroll
    for (int j = 1; j < cEF; j++) if (v[j] > b1) { b1 = v[j]; i1 = j; }
    int i2 = -1; float b2 = -1e30f;
#pragma unroll
    for (int j = 0; j < cEF; j++) if (j != i1 && v[j] > b2) { b2 = v[j]; i2 = j; }
    float e = expf(b2 - b1);
    float inv = 1.f / (1.f + e);
    g_top_e[2 * n] = i1; g_top_e[2 * n + 1] = i2;
    g_top_p[2 * n] = inv; g_top_p[2 * n + 1] = e * inv;
}

__global__ void routeff_kernel(float* __restrict__ out, int out_size) {
    __shared__ int eids[cN * 2];
    __shared__ int spos[cN * 2];
    __shared__ float scnt[cEF], simp[cEF];
    int t = threadIdx.x;
    for (int i = t; i < cN * 2; i += 256) eids[i] = g_top_e[i];
    if (t < cEF) { scnt[t] = 0.f; simp[t] = 0.f; }
    __syncthreads();
    if (t == 0) {
        int c[cEF];
#pragma unroll
        for (int e = 0; e < cEF; e++) c[e] = 0;
        for (int i = 0; i < cN * 2; i++) spos[i] = c[eids[i]]++;
    }
    __syncthreads();
    for (int n = t; n < cN; n += 256) {
        float p0 = g_top_p[2 * n], p1 = g_top_p[2 * n + 1];
        int pos0 = spos[2 * n], pos1 = spos[2 * n + 1];
        float q0 = (pos0 < cCAP) ? p0 : 0.f;
        float q1 = (pos1 < cCAP) ? p1 : 0.f;
        float inv = 1.f / (q0 + q1 + 1e-9f);
        float w0 = q0 * inv, w1 = q1 * inv;
        g_w[2 * n] = w0; g_w[2 * n + 1] = w1;
        g_pos[2 * n] = pos0; g_pos[2 * n + 1] = pos1;
        if (w0 > 0.f) { atomicAdd(&scnt[eids[2 * n]], 1.f); atomicAdd(&simp[eids[2 * n]], w0); }
        if (w1 > 0.f) { atomicAdd(&scnt[eids[2 * n + 1]], 1.f); atomicAdd(&simp[eids[2 * n + 1]], w1); }
    }
    __syncthreads();
    if (t == 0 && out_size > cN * cD) {
        // aux2
        float cs = 0.f, is = 0.f;
        for (int e = 0; e < cEF; e++) { cs += scnt[e]; is += simp[e]; }
        float aux2 = 0.f;
        for (int e = 0; e < cEF; e++)
            aux2 += (scnt[e] / (cs + 1e-9f)) * (simp[e] / (is + 1e-9f));
        aux2 *= cEF;
        // aux1 from router hard counts
        float ema[cH * cEA], es = 0.f;
        for (int i = 0; i < cH * cEA; i++) { ema[i] = 0.01f * g_hard[i] / (float)cN; es += ema[i]; }
        float aux1 = 0.f;
        for (int i = 0; i < cH * cEA; i++) { float pr = ema[i] / (es + 1e-9f); aux1 += pr * pr; }
        aux1 *= (float)(cEA * cH);
        out[cN * cD] = aux1 + aux2;
    }
}

__global__ void dispatch_kernel() {
    int a = blockIdx.x;
    int pos = g_pos[a];
    if (pos >= cCAP) return;
    int e = g_top_e[a];
    int n = a >> 1;
    float* dst = g_buf + ((long)e * cCAP + pos) * cD;
    const float* src = g_h2 + (long)n * cD;
    for (int i = threadIdx.x; i < cD; i += 256) dst[i] = src[i];
}

__global__ void combine_kernel(float* __restrict__ out) {
    int n = blockIdx.x;
    int e0 = g_top_e[2 * n], p0 = g_pos[2 * n];
    int e1 = g_top_e[2 * n + 1], p1 = g_pos[2 * n + 1];
    float w0 = g_w[2 * n], w1 = g_w[2 * n + 1];
    const float* y0 = g_ybuf + ((long)e0 * cCAP + (p0 < cCAP ? p0 : 0)) * cD;
    const float* y1 = g_ybuf + ((long)e1 * cCAP + (p1 < cCAP ? p1 : 0)) * cD;
    bool k0 = w0 > 0.f, k1 = w1 > 0.f;
    for (int i = threadIdx.x; i < cD; i += 256) {
        float v = g_x1[(long)n * cD + i];
        if (k0) v += w0 * y0[i];
        if (k1) v += w1 * y1[i];
        out[(long)n * cD + i] = v;
    }
}

// ---------------- launch ----------------
extern "C" void kernel_launch(void* const* d_in, const int* in_sizes, int n_in,
                              void* d_out, int out_size) {
    const float* x        = (const float*)d_in[0];
    const float* mask     = (const float*)d_in[1];
    const float* ln1_g    = (const float*)d_in[2];
    const float* ln1_b    = (const float*)d_in[3];
    const float* ln2_g    = (const float*)d_in[4];
    const float* ln2_b    = (const float*)d_in[5];
    const float* W_q      = (const float*)d_in[6];
    const float* W_k      = (const float*)d_in[7];
    const float* W_v      = (const float*)d_in[8];
    const float* W_o      = (const float*)d_in[9];
    const float* router_w = (const float*)d_in[10];
    const float* gate_w   = (const float*)d_in[11];
    const float* W1       = (const float*)d_in[12];
    const float* W2       = (const float*)d_in[13];
    float* out = (float*)d_out;

    static float *p_h1, *p_q, *p_k, *p_gate, *p_p, *p_vproj, *p_attnout,
                 *p_x1, *p_h2, *p_buf, *p_hmid, *p_ybuf;
    static bool init = false;
    if (!init) {
        cudaGetSymbolAddress((void**)&p_h1, g_h1);
        cudaGetSymbolAddress((void**)&p_q, g_q);
        cudaGetSymbolAddress((void**)&p_k, g_k);
        cudaGetSymbolAddress((void**)&p_gate, g_gate);
        cudaGetSymbolAddress((void**)&p_p, g_p);
        cudaGetSymbolAddress((void**)&p_vproj, g_vproj);
        cudaGetSymbolAddress((void**)&p_attnout, g_attnout);
        cudaGetSymbolAddress((void**)&p_x1, g_x1);
        cudaGetSymbolAddress((void**)&p_h2, g_h2);
        cudaGetSymbolAddress((void**)&p_buf, g_buf);
        cudaGetSymbolAddress((void**)&p_hmid, g_hmid);
        cudaGetSymbolAddress((void**)&p_ybuf, g_ybuf);
        init = true;
    }

    zero_kernel<<<1, 64>>>();
    // LN1
    ln_kernel<<<cN, 256>>>(x, ln1_g, ln1_b, p_h1);
    // Q, K, router projections
    gemm_nn<<<dim3(cD / 64, cN / 64, 1), 256>>>(p_h1, W_q, p_q, cN, cD, cD, cD, cD, cD,
                                                1, 0, 0, 0, 0, 0, 0, 0);
    gemm_nn<<<dim3(cD / 64, cN / 64, 1), 256>>>(p_h1, W_k, p_k, cN, cD, cD, cD, cD, cD,
                                                1, 0, 0, 0, 0, 0, 0, 0);
    gemm_nn<<<dim3(1, cN / 64, 1), 256>>>(p_h1, router_w, p_gate, cN, cH * cEA, cD,
                                          cD, cH * cEA, cH * cEA, 1, 0, 0, 0, 0, 0, 0, 0);
    argmax_kernel<<<cN, 16>>>();
    // scores = Q K^T (batched over b,h)
    gemm_nt<<<dim3(cS / 64, cS / 64, cB * cH), 256>>>(
        p_q, p_k, p_p, cS, cS, cDH, cD, cD, cS,
        cH, (long)cS * cD, 64, (long)cS * cD, 64, (long)cH * cS * cS, (long)cS * cS);
    softmax_kernel<<<cB * cH * cS, 256>>>(mask);
    // per-token expert V projection
    vproj_kernel<<<dim3(cN, cH), 64>>>(W_v);
    // attn_out = P^T V  (contracts the QUERY dim, per reference einsum)
    gemm_tn<<<dim3(1, cS / 64, cB * cH), 256>>>(
        p_p, p_vproj, p_attnout, cS, cDH, cS, cS, cDH, cDH,
        cH, (long)cH * cS * cS, (long)cS * cS,
        (long)cS * cDH, (long)cB * cS * cDH, (long)cS * cDH, (long)cB * cS * cDH);
    // per-token expert O projection + residual -> x1
    oproj_kernel<<<dim3(cN, cH), 64>>>(W_o, x);
    // LN2
    ln_kernel<<<cN, 256>>>(p_x1, ln2_g, ln2_b, p_h2);
    // MoE routing
    gateff_kernel<<<cN, 256>>>(gate_w);
    topk_kernel<<<cN / 128, 128>>>();
    routeff_kernel<<<1, 256>>>(out, out_size);
    dispatch_kernel<<<cN * 2, 256>>>();
    // FFN expert GEMMs
    gemm_nn<<<dim3(cDFF / 64, (cCAP + 63) / 64, cEF), 256>>>(
        p_buf, W1, p_hmid, cCAP, cDFF, cD, cD, cDFF, cDFF,
        1, (long)cCAP * cD, 0, (long)cD * cDFF, 0, (long)cCAP * cDFF, 0, 1);
    gemm_nn<<<dim3(cD / 64, (cCAP + 63) / 64, cEF), 256>>>(
        p_hmid, W2, p_ybuf, cCAP, cD, cDFF, cDFF, cD, cD,
        1, (long)cCAP * cDFF, 0, (long)cDFF * cD, 0, (long)cCAP * cD, 0, 0);
    // combine + residual -> out
    combine_kernel<<<cN, 256>>>(out);
}

// round 10
// speedup vs baseline: 1.2697x; 1.2697x over previous
#include <cuda_runtime.h>
#include <cuda_bf16.h>
#include <math.h>

// ---------------- problem constants ----------------
static constexpr int cB = 2, cS = 512, cD = 768, cH = 12, cDH = 64;
static constexpr int cEA = 4, cEF = 8, cDFF = 3072, cN = 1024, cCAP = 160;

// ---------------- scratch (device globals) ----------
__device__ float g_h1[cN * cD];
__device__ float g_qk[2 * cN * cD];                       // [0]=Q, [1]=K
__device__ float g_gate[cN * cH * cEA];
__device__ float g_p[(size_t)cB * cH * cS * cS];          // scores -> probs
__device__ int   g_aidx[cN * cH];
__device__ float g_hard[cH * cEA];
__device__ float g_vproj[cH * cB * cS * cDH];             // (h,b,s,d)
__device__ float g_attnout[cH * cB * cS * cDH];           // (h,b,t,d)
__device__ float g_x1[cN * cD];
__device__ float g_h2[cN * cD];
__device__ float g_gl[cN * cEF];
__device__ int   g_top_e[cN * 2];
__device__ float g_top_p[cN * 2];
__device__ int   g_pos[cN * 2];
__device__ float g_w[cN * 2];
__device__ float g_buf[cEF * cCAP * cD];
__device__ float g_hmid[(size_t)cEF * cCAP * cDFF];
__device__ float g_ybuf[cEF * cCAP * cD];

// ---------------- small kernels ----------------
__global__ void zero_kernel() {
    int t = threadIdx.x;
    if (t < cH * cEA) g_hard[t] = 0.f;
}

__global__ void ln_kernel(const float* __restrict__ in, const float* __restrict__ gam,
                          const float* __restrict__ bet, float* __restrict__ out) {
    int row = blockIdx.x;
    const float* r = in + (size_t)row * cD;
    __shared__ float red[256];
    int t = threadIdx.x;
    float s = 0.f;
    for (int i = t; i < cD; i += 256) s += r[i];
    red[t] = s; __syncthreads();
    for (int o = 128; o > 0; o >>= 1) { if (t < o) red[t] += red[t + o]; __syncthreads(); }
    float mu = red[0] / cD;
    __syncthreads();
    float s2 = 0.f;
    for (int i = t; i < cD; i += 256) { float d = r[i] - mu; s2 += d * d; }
    red[t] = s2; __syncthreads();
    for (int o = 128; o > 0; o >>= 1) { if (t < o) red[t] += red[t + o]; __syncthreads(); }
    float inv = rsqrtf(red[0] / cD + 1e-5f);
    for (int i = t; i < cD; i += 256)
        out[(size_t)row * cD + i] = (r[i] - mu) * inv * gam[i] + bet[i];
}

// ---------------- bf16-split tensor-core GEMM (NN) ----------------
// C = A(MxK) * B(KxN), fp32 in/out, computed as (Ah+Al)(Bh+Bl) dropping Al*Bl.
// If B2 != nullptr and blockIdx.z>0, B2 is used instead of B.
__device__ __forceinline__ void mma16816(float* d, const unsigned* a, const unsigned* b) {
    asm volatile(
        "mma.sync.aligned.m16n8k16.row.col.f32.bf16.bf16.f32 "
        "{%0,%1,%2,%3}, {%4,%5,%6,%7}, {%8,%9}, {%0,%1,%2,%3};"
        : "+f"(d[0]), "+f"(d[1]), "+f"(d[2]), "+f"(d[3])
        : "r"(a[0]), "r"(a[1]), "r"(a[2]), "r"(a[3]), "r"(b[0]), "r"(b[1]));
}

__device__ __forceinline__ void bsplit(float x, __nv_bfloat16& h, __nv_bfloat16& l) {
    h = __float2bfloat16(x);
    l = __float2bfloat16(x - __bfloat162float(h));
}

template<bool RELU>
__global__ __launch_bounds__(256) void hgemm(
    const float* __restrict__ A, const float* __restrict__ B,
    const float* __restrict__ B2, float* __restrict__ C,
    int M, int N, int K, int lda, int ldb, int ldc,
    long sA1, long sB1, long sC1)
{
    constexpr int BK = 32;
    int zb = blockIdx.z;
    A += (long)zb * sA1;
    const float* Bp = (B2 != nullptr && zb > 0) ? B2 : B;
    Bp += (long)zb * sB1;
    C += (long)zb * sC1;

    __shared__ __nv_bfloat16 Ah[64][BK + 8], Al[64][BK + 8];
    __shared__ __nv_bfloat16 Bh[64][BK + 8], Bl[64][BK + 8];

    const int tid = threadIdx.x;
    const int m0 = blockIdx.y * 64, n0 = blockIdx.x * 64;
    const int wid = tid >> 5, lane = tid & 31;
    const int wm = (wid & 3) * 16, wn = (wid >> 2) * 32;
    const int g = lane >> 2, t4 = lane & 3;

    float acc[4][4] = {};

    const int nt = K / BK;
    for (int kt = 0; kt < nt; kt++) {
        int k0 = kt * BK;
        // load + split A tile (64x32)
#pragma unroll
        for (int it = 0; it < 2; it++) {
            int idx = tid * 4 + it * 1024;
            int r = idx >> 5, c = idx & 31;
            float4 v = make_float4(0.f, 0.f, 0.f, 0.f);
            if (m0 + r < M) v = *(const float4*)(A + (long)(m0 + r) * lda + k0 + c);
            bsplit(v.x, Ah[r][c + 0], Al[r][c + 0]);
            bsplit(v.y, Ah[r][c + 1], Al[r][c + 1]);
            bsplit(v.z, Ah[r][c + 2], Al[r][c + 2]);
            bsplit(v.w, Ah[r][c + 3], Al[r][c + 3]);
        }
        // load + split B tile (32x64), transposed into smem [n][k]
#pragma unroll
        for (int it = 0; it < 2; it++) {
            int idx = tid * 4 + it * 1024;
            int r = idx >> 6, c = idx & 63;
            float4 v = make_float4(0.f, 0.f, 0.f, 0.f);
            if (n0 + c < N) v = *(const float4*)(Bp + (long)(k0 + r) * ldb + n0 + c);
            bsplit(v.x, Bh[c + 0][r], Bl[c + 0][r]);
            bsplit(v.y, Bh[c + 1][r], Bl[c + 1][r]);
            bsplit(v.z, Bh[c + 2][r], Bl[c + 2][r]);
            bsplit(v.w, Bh[c + 3][r], Bl[c + 3][r]);
        }
        __syncthreads();
#pragma unroll
        for (int ks = 0; ks < 2; ks++) {
            int kb = ks * 16;
            int r0 = wm + g;
            unsigned ah[4], al[4];
            ah[0] = *(const unsigned*)&Ah[r0][kb + t4 * 2];
            ah[1] = *(const unsigned*)&Ah[r0 + 8][kb + t4 * 2];
            ah[2] = *(const unsigned*)&Ah[r0][kb + t4 * 2 + 8];
            ah[3] = *(const unsigned*)&Ah[r0 + 8][kb + t4 * 2 + 8];
            al[0] = *(const unsigned*)&Al[r0][kb + t4 * 2];
            al[1] = *(const unsigned*)&Al[r0 + 8][kb + t4 * 2];
            al[2] = *(const unsigned*)&Al[r0][kb + t4 * 2 + 8];
            al[3] = *(const unsigned*)&Al[r0 + 8][kb + t4 * 2 + 8];
#pragma unroll
            for (int f = 0; f < 4; f++) {
                int n = wn + f * 8 + g;
                unsigned bh[2], bl[2];
                bh[0] = *(const unsigned*)&Bh[n][kb + t4 * 2];
                bh[1] = *(const unsigned*)&Bh[n][kb + t4 * 2 + 8];
                bl[0] = *(const unsigned*)&Bl[n][kb + t4 * 2];
                bl[1] = *(const unsigned*)&Bl[n][kb + t4 * 2 + 8];
                mma16816(acc[f], ah, bh);
                mma16816(acc[f], ah, bl);
                mma16816(acc[f], al, bh);
            }
        }
        __syncthreads();
    }

#pragma unroll
    for (int f = 0; f < 4; f++) {
        int n = n0 + wn + f * 8 + t4 * 2;
        int m = m0 + wm + g;
        float c0 = acc[f][0], c1 = acc[f][1], c2 = acc[f][2], c3 = acc[f][3];
        if (RELU) {
            c0 = fmaxf(c0, 0.f); c1 = fmaxf(c1, 0.f);
            c2 = fmaxf(c2, 0.f); c3 = fmaxf(c3, 0.f);
        }
        if (n < N) {
            if (m < M)     { C[(long)m * ldc + n] = c0;       C[(long)m * ldc + n + 1] = c1; }
            if (m + 8 < M) { C[(long)(m + 8) * ldc + n] = c2; C[(long)(m + 8) * ldc + n + 1] = c3; }
        }
    }
}

// ---------------- templated double-buffered SGEMM ----------------
// MODE 0: C = A(MxK)   * B(KxN)
// MODE 1: C = A(MxK)   * B(NxK)^T
// MODE 2: C = A(KxM)^T * B(KxN)
template<int MODE, int BM, int BN, int TM, int TN, bool RELU>
__global__ __launch_bounds__(256) void sgemm(
    const float* __restrict__ A, const float* __restrict__ B,
    const float* __restrict__ B2, float* __restrict__ C,
    int M, int N, int K, int lda, int ldb, int ldc,
    int zdiv, long sA1, long sA2, long sB1, long sB2, long sC1, long sC2)
{
    constexpr int BK = 8;
    int zb = blockIdx.z / zdiv, zi = blockIdx.z % zdiv;
    A += (long)zb * sA1 + (long)zi * sA2;
    const float* Bp = (B2 != nullptr && zb > 0) ? B2 : B;
    Bp += (long)zb * sB1 + (long)zi * sB2;
    C += (long)zb * sC1 + (long)zi * sC2;

    __shared__ float As[2][BK][BM + 4];
    __shared__ float Bs[2][BK][BN + 4];

    const int tid = threadIdx.x;
    const int m0 = blockIdx.y * BM, n0 = blockIdx.x * BN;

    constexpr int ACNT = BM * BK / 4;
    constexpr int BCNT = BN * BK / 4;

    int a_r, a_c;
    if constexpr (MODE != 2) { a_r = tid >> 1; a_c = (tid & 1) * 4; }
    else { a_r = tid / (BM / 4); a_c = (tid % (BM / 4)) * 4; }
    int b_r, b_c;
    if constexpr (MODE != 1) { b_r = tid / (BN / 4); b_c = (tid % (BN / 4)) * 4; }
    else { b_r = tid >> 1; b_c = (tid & 1) * 4; }

    auto fetchA = [&](int k0, float4& v) {
        v = make_float4(0.f, 0.f, 0.f, 0.f);
        if (tid < ACNT) {
            if constexpr (MODE != 2) {
                if (m0 + a_r < M) v = *(const float4*)(A + (long)(m0 + a_r) * lda + k0 + a_c);
            } else {
                if (m0 + a_c < M) v = *(const float4*)(A + (long)(k0 + a_r) * lda + m0 + a_c);
            }
        }
    };
    auto fetchB = [&](int k0, float4& v) {
        v = make_float4(0.f, 0.f, 0.f, 0.f);
        if (tid < BCNT) {
            if constexpr (MODE != 1) {
                if (n0 + b_c < N) v = *(const float4*)(Bp + (long)(k0 + b_r) * ldb + n0 + b_c);
            } else {
                if (n0 + b_r < N) v = *(const float4*)(Bp + (long)(n0 + b_r) * ldb + k0 + b_c);
            }
        }
    };
    auto storeA = [&](int buf, float4 v) {
        if (tid < ACNT) {
            if constexpr (MODE != 2) {
                As[buf][a_c + 0][a_r] = v.x; As[buf][a_c + 1][a_r] = v.y;
                As[buf][a_c + 2][a_r] = v.z; As[buf][a_c + 3][a_r] = v.w;
            } else {
                *(float4*)&As[buf][a_r][a_c] = v;
            }
        }
    };
    auto storeB = [&](int buf, float4 v) {
        if (tid < BCNT) {
            if constexpr (MODE != 1) {
                *(float4*)&Bs[buf][b_r][b_c] = v;
            } else {
                Bs[buf][b_c + 0][b_r] = v.x; Bs[buf][b_c + 1][b_r] = v.y;
                Bs[buf][b_c + 2][b_r] = v.z; Bs[buf][b_c + 3][b_r] = v.w;
            }
        }
    };

    constexpr int TX = BN / TN;
    const int tx = tid % TX, ty = tid / TX;

    float acc[TM][TN] = {};

    float4 fa, fb;
    fetchA(0, fa); fetchB(0, fb);
    storeA(0, fa); storeB(0, fb);
    __syncthreads();

    const int nt = K / BK;
    for (int t = 0; t < nt; t++) {
        int cur = t & 1;
        if (t + 1 < nt) { fetchA((t + 1) * BK, fa); fetchB((t + 1) * BK, fb); }
#pragma unroll
        for (int k = 0; k < BK; k++) {
            float a[TM], b[TN];
#pragma unroll
            for (int i = 0; i < TM; i += 4)
                *(float4*)&a[i] = *(const float4*)&As[cur][k][ty * TM + i];
#pragma unroll
            for (int j = 0; j < TN; j += 4)
                *(float4*)&b[j] = *(const float4*)&Bs[cur][k][tx * TN + j];
#pragma unroll
            for (int i = 0; i < TM; i++)
#pragma unroll
                for (int j = 0; j < TN; j++)
                    acc[i][j] += a[i] * b[j];
        }
        if (t + 1 < nt) { storeA(cur ^ 1, fa); storeB(cur ^ 1, fb); }
        __syncthreads();
    }

#pragma unroll
    for (int i = 0; i < TM; i++) {
        int m = m0 + ty * TM + i;
        if (m < M) {
#pragma unroll
            for (int j = 0; j < TN; j++) {
                int n = n0 + tx * TN + j;
                if (n < N) {
                    float v = acc[i][j];
                    if (RELU) v = fmaxf(v, 0.f);
                    C[(long)m * ldc + n] = v;
                }
            }
        }
    }
}

// ---------------- attention pieces ----------------
__global__ void softmax_kernel(const float* __restrict__ mask) {
    long rid = blockIdx.x;           // (b*H + h)*S + s
    int s = (int)(rid % cS);
    float* row = g_p + rid * cS;
    int t = threadIdx.x;
    __shared__ float red[256];
    float v0 = row[t] * 0.125f + mask[(long)s * cS + t];
    float v1 = row[t + 256] * 0.125f + mask[(long)s * cS + t + 256];
    float m = fmaxf(v0, v1);
    red[t] = m; __syncthreads();
    for (int o = 128; o > 0; o >>= 1) { if (t < o) red[t] = fmaxf(red[t], red[t + o]); __syncthreads(); }
    float rowmax = red[0];
    __syncthreads();
    float e0 = expf(v0 - rowmax), e1 = expf(v1 - rowmax);
    red[t] = e0 + e1; __syncthreads();
    for (int o = 128; o > 0; o >>= 1) { if (t < o) red[t] += red[t + o]; __syncthreads(); }
    float inv = 1.f / red[0];
    row[t] = e0 * inv;
    row[t + 256] = e1 * inv;
}

__global__ void argmax_kernel() {
    int n = blockIdx.x, h = threadIdx.x;
    if (h >= cH) return;
    const float* g4 = g_gate + (long)n * (cH * cEA) + h * cEA;
    int bi = 0; float bv = g4[0];
#pragma unroll
    for (int ea = 1; ea < cEA; ea++) if (g4[ea] > bv) { bv = g4[ea]; bi = ea; }
    g_aidx[n * cH + h] = bi;
    atomicAdd(&g_hard[h * cEA + bi], 1.f);
}

__global__ void vproj_kernel(const float* __restrict__ Wv) {
    int n = blockIdx.x, h = blockIdx.y, e = threadIdx.x;
    __shared__ float xs[64];
    xs[e] = g_h1[(long)n * cD + h * cDH + e];
    __syncthreads();
    int ei = g_aidx[n * cH + h];
    const float* Wp = Wv + ((long)(h * cEA + ei) * cDH) * cDH;
    float acc = 0.f;
#pragma unroll 8
    for (int d = 0; d < cDH; d++) acc += xs[d] * Wp[d * cDH + e];
    int b = n >> 9, s = n & 511;
    g_vproj[(((long)(h * cB + b) * cS) + s) * cDH + e] = acc;
}

__global__ void oproj_kernel(const float* __restrict__ Wo, const float* __restrict__ x) {
    int n = blockIdx.x, h = blockIdx.y, e = threadIdx.x;
    int b = n >> 9, s = n & 511;
    __shared__ float xs[64];
    xs[e] = g_attnout[(((long)(h * cB + b) * cS) + s) * cDH + e];
    __syncthreads();
    int ei = g_aidx[n * cH + h];
    const float* Wp = Wo + ((long)(h * cEA + ei) * cDH) * cDH;
    float acc = 0.f;
#pragma unroll 8
    for (int d = 0; d < cDH; d++) acc += xs[d] * Wp[d * cDH + e];
    g_x1[(long)n * cD + h * cDH + e] = x[(long)n * cD + h * cDH + e] + acc;
}

// ---------------- MoE FFN pieces ----------------
__global__ void gateff_kernel(const float* __restrict__ gate_w) {
    int n = blockIdx.x;
    int w = threadIdx.x >> 5, lane = threadIdx.x & 31;
    float acc = 0.f;
    for (int d = lane; d < cD; d += 32)
        acc += g_h2[(long)n * cD + d] * gate_w[(long)d * cEF + w];
#pragma unroll
    for (int o = 16; o > 0; o >>= 1) acc += __shfl_down_sync(0xffffffffu, acc, o);
    if (lane == 0) g_gl[n * cEF + w] = acc;
}

__global__ void topk_kernel() {
    int n = blockIdx.x * blockDim.x + threadIdx.x;
    if (n >= cN) return;
    float v[cEF];
#pragma unroll
    for (int j = 0; j < cEF; j++) v[j] = g_gl[n * cEF + j];
    int i1 = 0; float b1 = v[0];
#pragma unroll
    for (int j = 1; j < cEF; j++) if (v[j] > b1) { b1 = v[j]; i1 = j; }
    int i2 = -1; float b2 = -1e30f;
#pragma unroll
    for (int j = 0; j < cEF; j++) if (j != i1 && v[j] > b2) { b2 = v[j]; i2 = j; }
    float e = expf(b2 - b1);
    float inv = 1.f / (1.f + e);
    g_top_e[2 * n] = i1; g_top_e[2 * n + 1] = i2;
    g_top_p[2 * n] = inv; g_top_p[2 * n + 1] = e * inv;
}

__global__ void routeff_kernel(float* __restrict__ out, int out_size) {
    __shared__ int eids[cN * 2];
    __shared__ int spos[cN * 2];
    __shared__ float scnt[cEF], simp[cEF];
    int t = threadIdx.x;
    for (int i = t; i < cN * 2; i += 256) eids[i] = g_top_e[i];
    if (t < cEF) { scnt[t] = 0.f; simp[t] = 0.f; }
    __syncthreads();
    if (t == 0) {
        int c[cEF];
#pragma unroll
        for (int e = 0; e < cEF; e++) c[e] = 0;
        for (int i = 0; i < cN * 2; i++) spos[i] = c[eids[i]]++;
    }
    __syncthreads();
    for (int n = t; n < cN; n += 256) {
        float p0 = g_top_p[2 * n], p1 = g_top_p[2 * n + 1];
        int pos0 = spos[2 * n], pos1 = spos[2 * n + 1];
        float q0 = (pos0 < cCAP) ? p0 : 0.f;
        float q1 = (pos1 < cCAP) ? p1 : 0.f;
        float inv = 1.f / (q0 + q1 + 1e-9f);
        float w0 = q0 * inv, w1 = q1 * inv;
        g_w[2 * n] = w0; g_w[2 * n + 1] = w1;
        g_pos[2 * n] = pos0; g_pos[2 * n + 1] = pos1;
        if (w0 > 0.f) { atomicAdd(&scnt[eids[2 * n]], 1.f); atomicAdd(&simp[eids[2 * n]], w0); }
        if (w1 > 0.f) { atomicAdd(&scnt[eids[2 * n + 1]], 1.f); atomicAdd(&simp[eids[2 * n + 1]], w1); }
    }
    __syncthreads();
    if (t == 0 && out_size > cN * cD) {
        float cs = 0.f, is = 0.f;
        for (int e = 0; e < cEF; e++) { cs += scnt[e]; is += simp[e]; }
        float aux2 = 0.f;
        for (int e = 0; e < cEF; e++)
            aux2 += (scnt[e] / (cs + 1e-9f)) * (simp[e] / (is + 1e-9f));
        aux2 *= cEF;
        float ema[cH * cEA], es = 0.f;
        for (int i = 0; i < cH * cEA; i++) { ema[i] = 0.01f * g_hard[i] / (float)cN; es += ema[i]; }
        float aux1 = 0.f;
        for (int i = 0; i < cH * cEA; i++) { float pr = ema[i] / (es + 1e-9f); aux1 += pr * pr; }
        aux1 *= (float)(cEA * cH);
        out[cN * cD] = aux1 + aux2;
    }
}

__global__ void dispatch_kernel() {
    int a = blockIdx.x;
    int pos = g_pos[a];
    if (pos >= cCAP) return;
    int e = g_top_e[a];
    int n = a >> 1;
    float4* dst = (float4*)(g_buf + ((long)e * cCAP + pos) * cD);
    const float4* src = (const float4*)(g_h2 + (long)n * cD);
    for (int i = threadIdx.x; i < cD / 4; i += 192) dst[i] = src[i];
}

__global__ void combine_kernel(float* __restrict__ out) {
    int n = blockIdx.x;
    int e0 = g_top_e[2 * n], p0 = g_pos[2 * n];
    int e1 = g_top_e[2 * n + 1], p1 = g_pos[2 * n + 1];
    float w0 = g_w[2 * n], w1 = g_w[2 * n + 1];
    const float* y0 = g_ybuf + ((long)e0 * cCAP + (p0 < cCAP ? p0 : 0)) * cD;
    const float* y1 = g_ybuf + ((long)e1 * cCAP + (p1 < cCAP ? p1 : 0)) * cD;
    bool k0 = w0 > 0.f, k1 = w1 > 0.f;
    for (int i = threadIdx.x; i < cD; i += 256) {
        float v = g_x1[(long)n * cD + i];
        if (k0) v += w0 * y0[i];
        if (k1) v += w1 * y1[i];
        out[(long)n * cD + i] = v;
    }
}

// ---------------- launch ----------------
extern "C" void kernel_launch(void* const* d_in, const int* in_sizes, int n_in,
                              void* d_out, int out_size) {
    const float* x        = (const float*)d_in[0];
    const float* mask     = (const float*)d_in[1];
    const float* ln1_g    = (const float*)d_in[2];
    const float* ln1_b    = (const float*)d_in[3];
    const float* ln2_g    = (const float*)d_in[4];
    const float* ln2_b    = (const float*)d_in[5];
    const float* W_q      = (const float*)d_in[6];
    const float* W_k      = (const float*)d_in[7];
    const float* W_v      = (const float*)d_in[8];
    const float* W_o      = (const float*)d_in[9];
    const float* router_w = (const float*)d_in[10];
    const float* gate_w   = (const float*)d_in[11];
    const float* W1       = (const float*)d_in[12];
    const float* W2       = (const float*)d_in[13];
    float* out = (float*)d_out;

    static float *p_h1, *p_qk, *p_gate, *p_p, *p_vproj, *p_attnout,
                 *p_x1, *p_h2, *p_buf, *p_hmid, *p_ybuf;
    static bool init = false;
    if (!init) {
        cudaGetSymbolAddress((void**)&p_h1, g_h1);
        cudaGetSymbolAddress((void**)&p_qk, g_qk);
        cudaGetSymbolAddress((void**)&p_gate, g_gate);
        cudaGetSymbolAddress((void**)&p_p, g_p);
        cudaGetSymbolAddress((void**)&p_vproj, g_vproj);
        cudaGetSymbolAddress((void**)&p_attnout, g_attnout);
        cudaGetSymbolAddress((void**)&p_x1, g_x1);
        cudaGetSymbolAddress((void**)&p_h2, g_h2);
        cudaGetSymbolAddress((void**)&p_buf, g_buf);
        cudaGetSymbolAddress((void**)&p_hmid, g_hmid);
        cudaGetSymbolAddress((void**)&p_ybuf, g_ybuf);
        init = true;
    }

    zero_kernel<<<1, 64>>>();
    ln_kernel<<<cN, 256>>>(x, ln1_g, ln1_b, p_h1);

    // Fused Q+K projection on tensor cores: z=0 -> W_q, z=1 -> W_k
    hgemm<false><<<dim3(cD / 64, cN / 64, 2), 256>>>(
        p_h1, W_q, W_k, p_qk, cN, cD, cD, cD, cD, cD,
        0, 0, (long)cN * cD);

    // Router projection stays exact fp32 (argmax decisions must not flip)
    sgemm<0, 128, 64, 8, 4, false><<<dim3(1, cN / 128, 1), 256>>>(
        p_h1, router_w, nullptr, p_gate, cN, cH * cEA, cD, cD, cH * cEA, cH * cEA,
        1, 0, 0, 0, 0, 0, 0);

    argmax_kernel<<<cN, 16>>>();

    // scores = Q K^T (batched over b,h), fp32
    sgemm<1, 128, 128, 8, 8, false><<<dim3(cS / 128, cS / 128, cB * cH), 256>>>(
        p_qk, p_qk + (long)cN * cD, nullptr, p_p, cS, cS, cDH, cD, cD, cS,
        cH, (long)cS * cD, cDH, (long)cS * cD, cDH, (long)cH * cS * cS, (long)cS * cS);

    softmax_kernel<<<cB * cH * cS, 256>>>(mask);
    vproj_kernel<<<dim3(cN, cH), 64>>>(W_v);

    // attn_out = P^T V  (contracts the QUERY dim, per reference einsum), fp32
    sgemm<2, 128, 64, 8, 4, false><<<dim3(1, cS / 128, cB * cH), 256>>>(
        p_p, p_vproj, nullptr, p_attnout, cS, cDH, cS, cS, cDH, cDH,
        cH, (long)cH * cS * cS, (long)cS * cS,
        (long)cS * cDH, (long)cB * cS * cDH, (long)cS * cDH, (long)cB * cS * cDH);

    oproj_kernel<<<dim3(cN, cH), 64>>>(W_o, x);
    ln_kernel<<<cN, 256>>>(p_x1, ln2_g, ln2_b, p_h2);

    gateff_kernel<<<cN, 256>>>(gate_w);       // exact fp32 (top-k decisions)
    topk_kernel<<<cN / 128, 128>>>();
    routeff_kernel<<<1, 256>>>(out, out_size);
    dispatch_kernel<<<cN * 2, 192>>>();

    // FFN expert GEMMs on tensor cores (z = expert)
    hgemm<true><<<dim3(cDFF / 64, (cCAP + 63) / 64, cEF), 256>>>(
        p_buf, W1, nullptr, p_hmid, cCAP, cDFF, cD, cD, cDFF, cDFF,
        (long)cCAP * cD, (long)cD * cDFF, (long)cCAP * cDFF);
    hgemm<false><<<dim3(cD / 64, (cCAP + 63) / 64, cEF), 256>>>(
        p_hmid, W2, nullptr, p_ybuf, cCAP, cD, cDFF, cDFF, cD, cD,
        (long)cCAP * cDFF, (long)cDFF * cD, (long)cCAP * cD);

    combine_kernel<<<cN, 256>>>(out);
}

// round 12
// speedup vs baseline: 1.5509x; 1.2214x over previous
#include <cuda_runtime.h>
#include <cuda_bf16.h>
#include <math.h>

// ---------------- problem constants ----------------
static constexpr int cB = 2, cS = 512, cD = 768, cH = 12, cDH = 64;
static constexpr int cEA = 4, cEF = 8, cDFF = 3072, cN = 1024, cCAP = 160;

// ---------------- scratch (device globals) ----------
__device__ float g_h1[cN * cD];
__device__ float g_qk[2 * cN * cD];                       // [0]=Q, [1]=K
__device__ float g_p[(size_t)cB * cH * cS * cS];          // scores -> probs
__device__ int   g_aidx[cN * cH];
__device__ float g_hard[cH * cEA];
__device__ float g_vproj[cH * cB * cS * cDH];             // (h,b,s,d)
__device__ float g_attnout[cH * cB * cS * cDH];           // (h,b,t,d)
__device__ float g_x1[cN * cD];
__device__ float g_h2[cN * cD];
__device__ float g_gl[cN * cEF];
__device__ int   g_top_e[cN * 2];
__device__ float g_top_p[cN * 2];
__device__ int   g_pos[cN * 2];
__device__ float g_w[cN * 2];
__device__ float g_buf[cEF * cCAP * cD];
__device__ float g_hmid[(size_t)cEF * cCAP * cDFF];
__device__ float g_ybuf[cEF * cCAP * cD];

// ---------------- small kernels ----------------
__global__ void zero_kernel() {
    int t = threadIdx.x;
    if (t < cH * cEA) g_hard[t] = 0.f;
}

__global__ void ln_kernel(const float* __restrict__ in, const float* __restrict__ gam,
                          const float* __restrict__ bet, float* __restrict__ out) {
    int row = blockIdx.x;
    const float* r = in + (size_t)row * cD;
    __shared__ float red[256];
    int t = threadIdx.x;
    float s = 0.f;
    for (int i = t; i < cD; i += 256) s += r[i];
    red[t] = s; __syncthreads();
    for (int o = 128; o > 0; o >>= 1) { if (t < o) red[t] += red[t + o]; __syncthreads(); }
    float mu = red[0] / cD;
    __syncthreads();
    float s2 = 0.f;
    for (int i = t; i < cD; i += 256) { float d = r[i] - mu; s2 += d * d; }
    red[t] = s2; __syncthreads();
    for (int o = 128; o > 0; o >>= 1) { if (t < o) red[t] += red[t + o]; __syncthreads(); }
    float inv = rsqrtf(red[0] / cD + 1e-5f);
    for (int i = t; i < cD; i += 256)
        out[(size_t)row * cD + i] = (r[i] - mu) * inv * gam[i] + bet[i];
}

// ---------------- fused router: projection + per-head argmax + hard counts --
__global__ __launch_bounds__(256) void router_kernel(const float* __restrict__ router_w) {
    constexpr int NO = cH * cEA;   // 48 outputs
    constexpr int CH = 128;        // d-chunk size
    __shared__ float xs[cD];
    __shared__ float Ws[CH][NO + 1];   // pad -> conflict-free strided reads
    __shared__ float gates[NO];
    int n = blockIdx.x, t = threadIdx.x;
    int warp = t >> 5, lane = t & 31;
    for (int i = t; i < cD; i += 256) xs[i] = g_h1[(long)n * cD + i];
    float acc[6] = {};                 // outputs o = warp + 8*j
    for (int c0 = 0; c0 < cD; c0 += CH) {
        __syncthreads();
        for (int i = t; i < CH * NO; i += 256) {
            int d = i / NO, o = i % NO;
            Ws[d][o] = router_w[(long)(c0 + d) * NO + o];
        }
        __syncthreads();
#pragma unroll
        for (int j = 0; j < 6; j++) {
            int o = warp + 8 * j;
            float a = 0.f;
#pragma unroll 4
            for (int dd = lane; dd < CH; dd += 32)
                a += xs[c0 + dd] * Ws[dd][o];
            acc[j] += a;
        }
    }
#pragma unroll
    for (int j = 0; j < 6; j++) {
        float a = acc[j];
#pragma unroll
        for (int off = 16; off > 0; off >>= 1) a += __shfl_down_sync(0xffffffffu, a, off);
        if (lane == 0) gates[warp + 8 * j] = a;
    }
    __syncthreads();
    if (t < cH) {
        const float* g4 = gates + t * cEA;
        int bi = 0; float bv = g4[0];
#pragma unroll
        for (int ea = 1; ea < cEA; ea++) if (g4[ea] > bv) { bv = g4[ea]; bi = ea; }
        g_aidx[n * cH + t] = bi;
        atomicAdd(&g_hard[t * cEA + bi], 1.f);
    }
}

// ---------------- bf16-split tensor-core GEMM ----------------
// fp32 in/out, computed as (Ah+Al)(Bh+Bl) dropping Al*Bl.
// BNT=false: C = A(MxK) * B(KxN)   (B row-major KxN)
// BNT=true : C = A(MxK) * B(NxK)^T (B row-major NxK)
// If B2 != nullptr and zb>0, B2 is used instead of B.
__device__ __forceinline__ void mma16816(float* d, const unsigned* a, const unsigned* b) {
    asm volatile(
        "mma.sync.aligned.m16n8k16.row.col.f32.bf16.bf16.f32 "
        "{%0,%1,%2,%3}, {%4,%5,%6,%7}, {%8,%9}, {%0,%1,%2,%3};"
        : "+f"(d[0]), "+f"(d[1]), "+f"(d[2]), "+f"(d[3])
        : "r"(a[0]), "r"(a[1]), "r"(a[2]), "r"(a[3]), "r"(b[0]), "r"(b[1]));
}

__device__ __forceinline__ void bsplit(float x, __nv_bfloat16& h, __nv_bfloat16& l) {
    h = __float2bfloat16(x);
    l = __float2bfloat16(x - __bfloat162float(h));
}

template<bool RELU, bool BNT>
__global__ __launch_bounds__(256) void hgemm(
    const float* __restrict__ A, const float* __restrict__ B,
    const float* __restrict__ B2, float* __restrict__ C,
    int M, int N, int K, int lda, int ldb, int ldc,
    int zdiv, long sA1, long sA2, long sB1, long sB2, long sC1, long sC2)
{
    constexpr int BK = 32;
    int zb = blockIdx.z / zdiv, zi = blockIdx.z % zdiv;
    A += (long)zb * sA1 + (long)zi * sA2;
    const float* Bp = (B2 != nullptr && zb > 0) ? B2 : B;
    Bp += (long)zb * sB1 + (long)zi * sB2;
    C += (long)zb * sC1 + (long)zi * sC2;

    __shared__ __nv_bfloat16 Ah[64][BK + 8], Al[64][BK + 8];
    __shared__ __nv_bfloat16 Bh[64][BK + 8], Bl[64][BK + 8];

    const int tid = threadIdx.x;
    const int m0 = blockIdx.y * 64, n0 = blockIdx.x * 64;
    const int wid = tid >> 5, lane = tid & 31;
    const int wm = (wid & 3) * 16, wn = (wid >> 2) * 32;
    const int g = lane >> 2, t4 = lane & 3;

    float acc[4][4] = {};

    const int nt = K / BK;
    for (int kt = 0; kt < nt; kt++) {
        int k0 = kt * BK;
        // load + split A tile (64 rows x 32 k)
#pragma unroll
        for (int it = 0; it < 2; it++) {
            int idx = tid * 4 + it * 1024;
            int r = idx >> 5, c = idx & 31;
            float4 v = make_float4(0.f, 0.f, 0.f, 0.f);
            if (m0 + r < M) v = *(const float4*)(A + (long)(m0 + r) * lda + k0 + c);
            bsplit(v.x, Ah[r][c + 0], Al[r][c + 0]);
            bsplit(v.y, Ah[r][c + 1], Al[r][c + 1]);
            bsplit(v.z, Ah[r][c + 2], Al[r][c + 2]);
            bsplit(v.w, Ah[r][c + 3], Al[r][c + 3]);
        }
        // load + split B tile into smem layout [n][k]
        if constexpr (BNT) {
            // B is (N x K) row-major: rows are n, direct copy
#pragma unroll
            for (int it = 0; it < 2; it++) {
                int idx = tid * 4 + it * 1024;
                int r = idx >> 5, c = idx & 31;     // r = n (0-63), c = k
                float4 v = make_float4(0.f, 0.f, 0.f, 0.f);
                if (n0 + r < N) v = *(const float4*)(Bp + (long)(n0 + r) * ldb + k0 + c);
                bsplit(v.x, Bh[r][c + 0], Bl[r][c + 0]);
                bsplit(v.y, Bh[r][c + 1], Bl[r][c + 1]);
                bsplit(v.z, Bh[r][c + 2], Bl[r][c + 2]);
                bsplit(v.w, Bh[r][c + 3], Bl[r][c + 3]);
            }
        } else {
            // B is (K x N) row-major: transpose into [n][k]
#pragma unroll
            for (int it = 0; it < 2; it++) {
                int idx = tid * 4 + it * 1024;
                int r = idx >> 6, c = idx & 63;     // r = k (0-31), c = n
                float4 v = make_float4(0.f, 0.f, 0.f, 0.f);
                if (n0 + c < N) v = *(const float4*)(Bp + (long)(k0 + r) * ldb + n0 + c);
                bsplit(v.x, Bh[c + 0][r], Bl[c + 0][r]);
                bsplit(v.y, Bh[c + 1][r], Bl[c + 1][r]);
                bsplit(v.z, Bh[c + 2][r], Bl[c + 2][r]);
                bsplit(v.w, Bh[c + 3][r], Bl[c + 3][r]);
            }
        }
        __syncthreads();
#pragma unroll
        for (int ks = 0; ks < 2; ks++) {
            int kb = ks * 16;
            int r0 = wm + g;
            unsigned ah[4], al[4];
            ah[0] = *(const unsigned*)&Ah[r0][kb + t4 * 2];
            ah[1] = *(const unsigned*)&Ah[r0 + 8][kb + t4 * 2];
            ah[2] = *(const unsigned*)&Ah[r0][kb + t4 * 2 + 8];
            ah[3] = *(const unsigned*)&Ah[r0 + 8][kb + t4 * 2 + 8];
            al[0] = *(const unsigned*)&Al[r0][kb + t4 * 2];
            al[1] = *(const unsigned*)&Al[r0 + 8][kb + t4 * 2];
            al[2] = *(const unsigned*)&Al[r0][kb + t4 * 2 + 8];
            al[3] = *(const unsigned*)&Al[r0 + 8][kb + t4 * 2 + 8];
#pragma unroll
            for (int f = 0; f < 4; f++) {
                int n = wn + f * 8 + g;
                unsigned bh[2], bl[2];
                bh[0] = *(const unsigned*)&Bh[n][kb + t4 * 2];
                bh[1] = *(const unsigned*)&Bh[n][kb + t4 * 2 + 8];
                bl[0] = *(const unsigned*)&Bl[n][kb + t4 * 2];
                bl[1] = *(const unsigned*)&Bl[n][kb + t4 * 2 + 8];
                mma16816(acc[f], ah, bh);
                mma16816(acc[f], ah, bl);
                mma16816(acc[f], al, bh);
            }
        }
        __syncthreads();
    }

#pragma unroll
    for (int f = 0; f < 4; f++) {
        int n = n0 + wn + f * 8 + t4 * 2;
        int m = m0 + wm + g;
        float c0 = acc[f][0], c1 = acc[f][1], c2 = acc[f][2], c3 = acc[f][3];
        if (RELU) {
            c0 = fmaxf(c0, 0.f); c1 = fmaxf(c1, 0.f);
            c2 = fmaxf(c2, 0.f); c3 = fmaxf(c3, 0.f);
        }
        if (n < N) {
            if (m < M)     { C[(long)m * ldc + n] = c0;       C[(long)m * ldc + n + 1] = c1; }
            if (m + 8 < M) { C[(long)(m + 8) * ldc + n] = c2; C[(long)(m + 8) * ldc + n + 1] = c3; }
        }
    }
}

// ---------------- templated double-buffered SGEMM ----------------
// MODE 0: C = A(MxK)   * B(KxN)
// MODE 1: C = A(MxK)   * B(NxK)^T
// MODE 2: C = A(KxM)^T * B(KxN)
template<int MODE, int BM, int BN, int TM, int TN, bool RELU>
__global__ __launch_bounds__(256) void sgemm(
    const float* __restrict__ A, const float* __restrict__ B,
    const float* __restrict__ B2, float* __restrict__ C,
    int M, int N, int K, int lda, int ldb, int ldc,
    int zdiv, long sA1, long sA2, long sB1, long sB2, long sC1, long sC2)
{
    constexpr int BK = 8;
    int zb = blockIdx.z / zdiv, zi = blockIdx.z % zdiv;
    A += (long)zb * sA1 + (long)zi * sA2;
    const float* Bp = (B2 != nullptr && zb > 0) ? B2 : B;
    Bp += (long)zb * sB1 + (long)zi * sB2;
    C += (long)zb * sC1 + (long)zi * sC2;

    __shared__ float As[2][BK][BM + 4];
    __shared__ float Bs[2][BK][BN + 4];

    const int tid = threadIdx.x;
    const int m0 = blockIdx.y * BM, n0 = blockIdx.x * BN;

    constexpr int ACNT = BM * BK / 4;
    constexpr int BCNT = BN * BK / 4;

    int a_r, a_c;
    if constexpr (MODE != 2) { a_r = tid >> 1; a_c = (tid & 1) * 4; }
    else { a_r = tid / (BM / 4); a_c = (tid % (BM / 4)) * 4; }
    int b_r, b_c;
    if constexpr (MODE != 1) { b_r = tid / (BN / 4); b_c = (tid % (BN / 4)) * 4; }
    else { b_r = tid >> 1; b_c = (tid & 1) * 4; }

    auto fetchA = [&](int k0, float4& v) {
        v = make_float4(0.f, 0.f, 0.f, 0.f);
        if (tid < ACNT) {
            if constexpr (MODE != 2) {
                if (m0 + a_r < M) v = *(const float4*)(A + (long)(m0 + a_r) * lda + k0 + a_c);
            } else {
                if (m0 + a_c < M) v = *(const float4*)(A + (long)(k0 + a_r) * lda + m0 + a_c);
            }
        }
    };
    auto fetchB = [&](int k0, float4& v) {
        v = make_float4(0.f, 0.f, 0.f, 0.f);
        if (tid < BCNT) {
            if constexpr (MODE != 1) {
                if (n0 + b_c < N) v = *(const float4*)(Bp + (long)(k0 + b_r) * ldb + n0 + b_c);
            } else {
                if (n0 + b_r < N) v = *(const float4*)(Bp + (long)(n0 + b_r) * ldb + k0 + b_c);
            }
        }
    };
    auto storeA = [&](int buf, float4 v) {
        if (tid < ACNT) {
            if constexpr (MODE != 2) {
                As[buf][a_c + 0][a_r] = v.x; As[buf][a_c + 1][a_r] = v.y;
                As[buf][a_c + 2][a_r] = v.z; As[buf][a_c + 3][a_r] = v.w;
            } else {
                *(float4*)&As[buf][a_r][a_c] = v;
            }
        }
    };
    auto storeB = [&](int buf, float4 v) {
        if (tid < BCNT) {
            if constexpr (MODE != 1) {
                *(float4*)&Bs[buf][b_r][b_c] = v;
            } else {
                Bs[buf][b_c + 0][b_r] = v.x; Bs[buf][b_c + 1][b_r] = v.y;
                Bs[buf][b_c + 2][b_r] = v.z; Bs[buf][b_c + 3][b_r] = v.w;
            }
        }
    };

    constexpr int TX = BN / TN;
    const int tx = tid % TX, ty = tid / TX;

    float acc[TM][TN] = {};

    float4 fa, fb;
    fetchA(0, fa); fetchB(0, fb);
    storeA(0, fa); storeB(0, fb);
    __syncthreads();

    const int nt = K / BK;
    for (int t = 0; t < nt; t++) {
        int cur = t & 1;
        if (t + 1 < nt) { fetchA((t + 1) * BK, fa); fetchB((t + 1) * BK, fb); }
#pragma unroll
        for (int k = 0; k < BK; k++) {
            float a[TM], b[TN];
#pragma unroll
            for (int i = 0; i < TM; i += 4)
                *(float4*)&a[i] = *(const float4*)&As[cur][k][ty * TM + i];
#pragma unroll
            for (int j = 0; j < TN; j += 4)
                *(float4*)&b[j] = *(const float4*)&Bs[cur][k][tx * TN + j];
#pragma unroll
            for (int i = 0; i < TM; i++)
#pragma unroll
                for (int j = 0; j < TN; j++)
                    acc[i][j] += a[i] * b[j];
        }
        if (t + 1 < nt) { storeA(cur ^ 1, fa); storeB(cur ^ 1, fb); }
        __syncthreads();
    }

#pragma unroll
    for (int i = 0; i < TM; i++) {
        int m = m0 + ty * TM + i;
        if (m < M) {
#pragma unroll
            for (int j = 0; j < TN; j++) {
                int n = n0 + tx * TN + j;
                if (n < N) {
                    float v = acc[i][j];
                    if (RELU) v = fmaxf(v, 0.f);
                    C[(long)m * ldc + n] = v;
                }
            }
        }
    }
}

// ---------------- attention pieces ----------------
__global__ void softmax_kernel(const float* __restrict__ mask) {
    long rid = blockIdx.x;           // (b*H + h)*S + s
    int s = (int)(rid % cS);
    float* row = g_p + rid * cS;
    int t = threadIdx.x;
    __shared__ float red[256];
    float v0 = row[t] * 0.125f + mask[(long)s * cS + t];
    float v1 = row[t + 256] * 0.125f + mask[(long)s * cS + t + 256];
    float m = fmaxf(v0, v1);
    red[t] = m; __syncthreads();
    for (int o = 128; o > 0; o >>= 1) { if (t < o) red[t] = fmaxf(red[t], red[t + o]); __syncthreads(); }
    float rowmax = red[0];
    __syncthreads();
    float e0 = expf(v0 - rowmax), e1 = expf(v1 - rowmax);
    red[t] = e0 + e1; __syncthreads();
    for (int o = 128; o > 0; o >>= 1) { if (t < o) red[t] += red[t + o]; __syncthreads(); }
    float inv = 1.f / red[0];
    row[t] = e0 * inv;
    row[t + 256] = e1 * inv;
}

__global__ void vproj_kernel(const float* __restrict__ Wv) {
    int n = blockIdx.x, h = blockIdx.y, e = threadIdx.x;
    __shared__ float xs[64];
    xs[e] = g_h1[(long)n * cD + h * cDH + e];
    __syncthreads();
    int ei = g_aidx[n * cH + h];
    const float* Wp = Wv + ((long)(h * cEA + ei) * cDH) * cDH;
    float acc = 0.f;
#pragma unroll 8
    for (int d = 0; d < cDH; d++) acc += xs[d] * Wp[d * cDH + e];
    int b = n >> 9, s = n & 511;
    g_vproj[(((long)(h * cB + b) * cS) + s) * cDH + e] = acc;
}

__global__ void oproj_kernel(const float* __restrict__ Wo, const float* __restrict__ x) {
    int n = blockIdx.x, h = blockIdx.y, e = threadIdx.x;
    int b = n >> 9, s = n & 511;
    __shared__ float xs[64];
    xs[e] = g_attnout[(((long)(h * cB + b) * cS) + s) * cDH + e];
    __syncthreads();
    int ei = g_aidx[n * cH + h];
    const float* Wp = Wo + ((long)(h * cEA + ei) * cDH) * cDH;
    float acc = 0.f;
#pragma unroll 8
    for (int d = 0; d < cDH; d++) acc += xs[d] * Wp[d * cDH + e];
    g_x1[(long)n * cD + h * cDH + e] = x[(long)n * cD + h * cDH + e] + acc;
}

// ---------------- MoE FFN pieces ----------------
__global__ void gateff_kernel(const float* __restrict__ gate_w) {
    int n = blockIdx.x;
    int w = threadIdx.x >> 5, lane = threadIdx.x & 31;
    float acc = 0.f;
    for (int d = lane; d < cD; d += 32)
        acc += g_h2[(long)n * cD + d] * gate_w[(long)d * cEF + w];
#pragma unroll
    for (int o = 16; o > 0; o >>= 1) acc += __shfl_down_sync(0xffffffffu, acc, o);
    if (lane == 0) g_gl[n * cEF + w] = acc;
}

__global__ void topk_kernel() {
    int n = blockIdx.x * blockDim.x + threadIdx.x;
    if (n >= cN) return;
    float v[cEF];
#pragma unroll
    for (int j = 0; j < cEF; j++) v[j] = g_gl[n * cEF + j];
    int i1 = 0; float b1 = v[0];
#pragma unroll
    for (int j = 1; j < cEF; j++) if (v[j] > b1) { b1 = v[j]; i1 = j; }
    int i2 = -1; float b2 = -1e30f;
#pragma unroll
    for (int j = 0; j < cEF; j++) if (j != i1 && v[j] > b2) { b2 = v[j]; i2 = j; }
    float e = expf(b2 - b1);
    float inv = 1.f / (1.f + e);
    g_top_e[2 * n] = i1; g_top_e[2 * n + 1] = i2;
    g_top_p[2 * n] = inv; g_top_p[2 * n + 1] = e * inv;
}

__global__ void routeff_kernel(float* __restrict__ out, int out_size) {
    __shared__ int eids[cN * 2];
    __shared__ int spos[cN * 2];
    __shared__ float scnt[cEF], simp[cEF];
    int t = threadIdx.x;
    int warp = t >> 5, lane = t & 31;
    for (int i = t; i < cN * 2; i += 256) eids[i] = g_top_e[i];
    if (t < cEF) { scnt[t] = 0.f; simp[t] = 0.f; }
    __syncthreads();
    // warp-parallel per-expert sequential-position scan (token-major order preserved)
    if (warp < cEF) {
        int e = warp;
        int running = 0;
        for (int base = 0; base < cN * 2; base += 32) {
            int i = base + lane;
            bool match = (eids[i] == e);
            unsigned mk = __ballot_sync(0xffffffffu, match);
            if (match) spos[i] = running + __popc(mk & ((1u << lane) - 1u));
            running += __popc(mk);
        }
    }
    __syncthreads();
    for (int n = t; n < cN; n += 256) {
        float p0 = g_top_p[2 * n], p1 = g_top_p[2 * n + 1];
        int pos0 = spos[2 * n], pos1 = spos[2 * n + 1];
        float q0 = (pos0 < cCAP) ? p0 : 0.f;
        float q1 = (pos1 < cCAP) ? p1 : 0.f;
        float inv = 1.f / (q0 + q1 + 1e-9f);
        float w0 = q0 * inv, w1 = q1 * inv;
        g_w[2 * n] = w0; g_w[2 * n + 1] = w1;
        g_pos[2 * n] = pos0; g_pos[2 * n + 1] = pos1;
        if (w0 > 0.f) { atomicAdd(&scnt[eids[2 * n]], 1.f); atomicAdd(&simp[eids[2 * n]], w0); }
        if (w1 > 0.f) { atomicAdd(&scnt[eids[2 * n + 1]], 1.f); atomicAdd(&simp[eids[2 * n + 1]], w1); }
    }
    __syncthreads();
    if (t == 0 && out_size > cN * cD) {
        float cs = 0.f, is = 0.f;
        for (int e = 0; e < cEF; e++) { cs += scnt[e]; is += simp[e]; }
        float aux2 = 0.f;
        for (int e = 0; e < cEF; e++)
            aux2 += (scnt[e] / (cs + 1e-9f)) * (simp[e] / (is + 1e-9f));
        aux2 *= cEF;
        float ema[cH * cEA], es = 0.f;
        for (int i = 0; i < cH * cEA; i++) { ema[i] = 0.01f * g_hard[i] / (float)cN; es += ema[i]; }
        float aux1 = 0.f;
        for (int i = 0; i < cH * cEA; i++) { float pr = ema[i] / (es + 1e-9f); aux1 += pr * pr; }
        aux1 *= (float)(cEA * cH);
        out[cN * cD] = aux1 + aux2;
    }
}

__global__ void dispatch_kernel() {
    int a = blockIdx.x;
    int pos = g_pos[a];
    if (pos >= cCAP) return;
    int e = g_top_e[a];
    int n = a >> 1;
    float4* dst = (float4*)(g_buf + ((long)e * cCAP + pos) * cD);
    const float4* src = (const float4*)(g_h2 + (long)n * cD);
    for (int i = threadIdx.x; i < cD / 4; i += 192) dst[i] = src[i];
}

__global__ void combine_kernel(float* __restrict__ out) {
    int n = blockIdx.x;
    int e0 = g_top_e[2 * n], p0 = g_pos[2 * n];
    int e1 = g_top_e[2 * n + 1], p1 = g_pos[2 * n + 1];
    float w0 = g_w[2 * n], w1 = g_w[2 * n + 1];
    const float* y0 = g_ybuf + ((long)e0 * cCAP + (p0 < cCAP ? p0 : 0)) * cD;
    const float* y1 = g_ybuf + ((long)e1 * cCAP + (p1 < cCAP ? p1 : 0)) * cD;
    bool k0 = w0 > 0.f, k1 = w1 > 0.f;
    for (int i = threadIdx.x; i < cD; i += 256) {
        float v = g_x1[(long)n * cD + i];
        if (k0) v += w0 * y0[i];
        if (k1) v += w1 * y1[i];
        out[(long)n * cD + i] = v;
    }
}

// ---------------- launch ----------------
extern "C" void kernel_launch(void* const* d_in, const int* in_sizes, int n_in,
                              void* d_out, int out_size) {
    const float* x        = (const float*)d_in[0];
    const float* mask     = (const float*)d_in[1];
    const float* ln1_g    = (const float*)d_in[2];
    const float* ln1_b    = (const float*)d_in[3];
    const float* ln2_g    = (const float*)d_in[4];
    const float* ln2_b    = (const float*)d_in[5];
    const float* W_q      = (const float*)d_in[6];
    const float* W_k      = (const float*)d_in[7];
    const float* W_v      = (const float*)d_in[8];
    const float* W_o      = (const float*)d_in[9];
    const float* router_w = (const float*)d_in[10];
    const float* gate_w   = (const float*)d_in[11];
    const float* W1       = (const float*)d_in[12];
    const float* W2       = (const float*)d_in[13];
    float* out = (float*)d_out;

    static float *p_h1, *p_qk, *p_p, *p_vproj, *p_attnout,
                 *p_x1, *p_h2, *p_buf, *p_hmid, *p_ybuf;
    static bool init = false;
    if (!init) {
        cudaGetSymbolAddress((void**)&p_h1, g_h1);
        cudaGetSymbolAddress((void**)&p_qk, g_qk);
        cudaGetSymbolAddress((void**)&p_p, g_p);
        cudaGetSymbolAddress((void**)&p_vproj, g_vproj);
        cudaGetSymbolAddress((void**)&p_attnout, g_attnout);
        cudaGetSymbolAddress((void**)&p_x1, g_x1);
        cudaGetSymbolAddress((void**)&p_h2, g_h2);
        cudaGetSymbolAddress((void**)&p_buf, g_buf);
        cudaGetSymbolAddress((void**)&p_hmid, g_hmid);
        cudaGetSymbolAddress((void**)&p_ybuf, g_ybuf);
        init = true;
    }

    zero_kernel<<<1, 64>>>();
    ln_kernel<<<cN, 256>>>(x, ln1_g, ln1_b, p_h1);

    // Fused Q+K projection on tensor cores: z=0 -> W_q, z=1 -> W_k
    hgemm<false, false><<<dim3(cD / 64, cN / 64, 2), 256>>>(
        p_h1, W_q, W_k, p_qk, cN, cD, cD, cD, cD, cD,
        1, 0, 0, 0, 0, (long)cN * cD, 0);

    // Fused router projection + argmax + hard counts (fp32-exact decisions)
    router_kernel<<<cN, 256>>>(router_w);

    // scores = Q K^T on tensor cores (batched over b,h via zdiv)
    hgemm<false, true><<<dim3(cS / 64, cS / 64, cB * cH), 256>>>(
        p_qk, p_qk + (long)cN * cD, nullptr, p_p, cS, cS, cDH, cD, cD, cS,
        cH, (long)cS * cD, cDH, (long)cS * cD, cDH, (long)cH * cS * cS, (long)cS * cS);

    softmax_kernel<<<cB * cH * cS, 256>>>(mask);
    vproj_kernel<<<dim3(cN, cH), 64>>>(W_v);

    // attn_out = P^T V  (contracts the QUERY dim, per reference einsum), fp32
    sgemm<2, 128, 64, 8, 4, false><<<dim3(1, cS / 128, cB * cH), 256>>>(
        p_p, p_vproj, nullptr, p_attnout, cS, cDH, cS, cS, cDH, cDH,
        cH, (long)cH * cS * cS, (long)cS * cS,
        (long)cS * cDH, (long)cB * cS * cDH, (long)cS * cDH, (long)cB * cS * cDH);

    oproj_kernel<<<dim3(cN, cH), 64>>>(W_o, x);
    ln_kernel<<<cN, 256>>>(p_x1, ln2_g, ln2_b, p_h2);

    gateff_kernel<<<cN, 256>>>(gate_w);       // exact fp32 (top-k decisions)
    topk_kernel<<<cN / 128, 128>>>();
    routeff_kernel<<<1, 256>>>(out, out_size);
    dispatch_kernel<<<cN * 2, 192>>>();

    // FFN expert GEMMs on tensor cores (z = expert)
    hgemm<true, false><<<dim3(cDFF / 64, (cCAP + 63) / 64, cEF), 256>>>(
        p_buf, W1, nullptr, p_hmid, cCAP, cDFF, cD, cD, cDFF, cDFF,
        1, (long)cCAP * cD, 0, (long)cD * cDFF, 0, (long)cCAP * cDFF, 0);
    hgemm<false, false><<<dim3(cD / 64, (cCAP + 63) / 64, cEF), 256>>>(
        p_hmid, W2, nullptr, p_ybuf, cCAP, cD, cDFF, cDFF, cD, cD,
        1, (long)cCAP * cDFF, 0, (long)cDFF * cD, 0, (long)cCAP * cD, 0);

    combine_kernel<<<cN, 256>>>(out);
}

// round 14
// speedup vs baseline: 1.6198x; 1.0444x over previous
#include <cuda_runtime.h>
#include <cuda_bf16.h>
#include <math.h>

// ---------------- problem constants ----------------
static constexpr int cB = 2, cS = 512, cD = 768, cH = 12, cDH = 64;
static constexpr int cEA = 4, cEF = 8, cDFF = 3072, cN = 1024, cCAP = 160;

// ---------------- scratch (device globals) ----------
__device__ float g_h1[cN * cD];
__device__ float g_qk[2 * cN * cD];                       // [0]=Q, [1]=K
__device__ float g_p[(size_t)cB * cH * cS * cS];          // scores -> probs
__device__ int   g_aidx[cN * cH];
__device__ float g_hard[cH * cEA];
__device__ float g_vproj[cH * cB * cS * cDH];             // (h,b,s,d)
__device__ float g_attnout[cH * cB * cS * cDH];           // (h,b,t,d)
__device__ float g_x1[cN * cD];
__device__ float g_h2[cN * cD];
__device__ float g_gl[cN * cEF];
__device__ int   g_top_e[cN * 2];
__device__ float g_top_p[cN * 2];
__device__ int   g_pos[cN * 2];
__device__ float g_w[cN * 2];
__device__ float g_buf[cEF * cCAP * cD];
__device__ float g_hmid[(size_t)cEF * cCAP * cDFF];
__device__ float g_ybuf[cEF * cCAP * cD];

// ---------------- small kernels ----------------
__global__ void zero_kernel() {
    int t = threadIdx.x;
    if (t < cH * cEA) g_hard[t] = 0.f;
}

__global__ void ln_kernel(const float* __restrict__ in, const float* __restrict__ gam,
                          const float* __restrict__ bet, float* __restrict__ out) {
    int row = blockIdx.x;
    const float* r = in + (size_t)row * cD;
    __shared__ float red[256];
    int t = threadIdx.x;
    float s = 0.f;
    for (int i = t; i < cD; i += 256) s += r[i];
    red[t] = s; __syncthreads();
    for (int o = 128; o > 0; o >>= 1) { if (t < o) red[t] += red[t + o]; __syncthreads(); }
    float mu = red[0] / cD;
    __syncthreads();
    float s2 = 0.f;
    for (int i = t; i < cD; i += 256) { float d = r[i] - mu; s2 += d * d; }
    red[t] = s2; __syncthreads();
    for (int o = 128; o > 0; o >>= 1) { if (t < o) red[t] += red[t + o]; __syncthreads(); }
    float inv = rsqrtf(red[0] / cD + 1e-5f);
    for (int i = t; i < cD; i += 256)
        out[(size_t)row * cD + i] = (r[i] - mu) * inv * gam[i] + bet[i];
}

// ---------------- fused router: projection + per-head argmax + hard counts --
__global__ __launch_bounds__(256) void router_kernel(const float* __restrict__ router_w) {
    constexpr int NO = cH * cEA;   // 48 outputs
    constexpr int CH = 128;        // d-chunk size
    __shared__ float xs[cD];
    __shared__ float Ws[CH][NO + 1];   // pad -> conflict-free strided reads
    __shared__ float gates[NO];
    int n = blockIdx.x, t = threadIdx.x;
    int warp = t >> 5, lane = t & 31;
    for (int i = t; i < cD; i += 256) xs[i] = g_h1[(long)n * cD + i];
    float acc[6] = {};                 // outputs o = warp + 8*j
    for (int c0 = 0; c0 < cD; c0 += CH) {
        __syncthreads();
        for (int i = t; i < CH * NO; i += 256) {
            int d = i / NO, o = i % NO;
            Ws[d][o] = router_w[(long)(c0 + d) * NO + o];
        }
        __syncthreads();
#pragma unroll
        for (int j = 0; j < 6; j++) {
            int o = warp + 8 * j;
            float a = 0.f;
#pragma unroll 4
            for (int dd = lane; dd < CH; dd += 32)
                a += xs[c0 + dd] * Ws[dd][o];
            acc[j] += a;
        }
    }
#pragma unroll
    for (int j = 0; j < 6; j++) {
        float a = acc[j];
#pragma unroll
        for (int off = 16; off > 0; off >>= 1) a += __shfl_down_sync(0xffffffffu, a, off);
        if (lane == 0) gates[warp + 8 * j] = a;
    }
    __syncthreads();
    if (t < cH) {
        const float* g4 = gates + t * cEA;
        int bi = 0; float bv = g4[0];
#pragma unroll
        for (int ea = 1; ea < cEA; ea++) if (g4[ea] > bv) { bv = g4[ea]; bi = ea; }
        g_aidx[n * cH + t] = bi;
        atomicAdd(&g_hard[t * cEA + bi], 1.f);
    }
}

// ---------------- bf16-split tensor-core GEMM (double-buffered) ------------
// fp32 in/out, computed as (Ah+Al)(Bh+Bl) dropping Al*Bl.
// ATR=false: A is (MxK) row-major.   ATR=true: A is (KxM) row-major (C = A^T B).
// BNT=false: B is (KxN) row-major.   BNT=true: B is (NxK) row-major (C = A B^T).
// If B2 != nullptr and zb>0, B2 is used instead of B.
__device__ __forceinline__ void mma16816(float* d, const unsigned* a, const unsigned* b) {
    asm volatile(
        "mma.sync.aligned.m16n8k16.row.col.f32.bf16.bf16.f32 "
        "{%0,%1,%2,%3}, {%4,%5,%6,%7}, {%8,%9}, {%0,%1,%2,%3};"
        : "+f"(d[0]), "+f"(d[1]), "+f"(d[2]), "+f"(d[3])
        : "r"(a[0]), "r"(a[1]), "r"(a[2]), "r"(a[3]), "r"(b[0]), "r"(b[1]));
}

__device__ __forceinline__ void bsplit(float x, __nv_bfloat16& h, __nv_bfloat16& l) {
    h = __float2bfloat16(x);
    l = __float2bfloat16(x - __bfloat162float(h));
}

template<bool RELU, bool BNT, bool ATR>
__global__ __launch_bounds__(256) void hgemm(
    const float* __restrict__ A, const float* __restrict__ B,
    const float* __restrict__ B2, float* __restrict__ C,
    int M, int N, int K, int lda, int ldb, int ldc,
    int zdiv, long sA1, long sA2, long sB1, long sB2, long sC1, long sC2)
{
    constexpr int BK = 32;
    int zb = blockIdx.z / zdiv, zi = blockIdx.z % zdiv;
    A += (long)zb * sA1 + (long)zi * sA2;
    const float* Bp = (B2 != nullptr && zb > 0) ? B2 : B;
    Bp += (long)zb * sB1 + (long)zi * sB2;
    C += (long)zb * sC1 + (long)zi * sC2;

    __shared__ __nv_bfloat16 Ah[2][64][BK + 8], Al[2][64][BK + 8];
    __shared__ __nv_bfloat16 Bh[2][64][BK + 8], Bl[2][64][BK + 8];

    const int tid = threadIdx.x;
    const int m0 = blockIdx.y * 64, n0 = blockIdx.x * 64;
    const int wid = tid >> 5, lane = tid & 31;
    const int wm = (wid & 3) * 16, wn = (wid >> 2) * 32;
    const int g = lane >> 2, t4 = lane & 3;

    float acc[4][4] = {};
    float4 fa[2], fb[2];

    auto fetch = [&](int k0) {
#pragma unroll
        for (int it = 0; it < 2; it++) {
            int idx = tid * 4 + it * 1024;
            // A
            fa[it] = make_float4(0.f, 0.f, 0.f, 0.f);
            if constexpr (ATR) {
                int r = idx >> 6, c = idx & 63;      // r = k (0..31), c = m
                if (m0 + c < M) fa[it] = *(const float4*)(A + (long)(k0 + r) * lda + m0 + c);
            } else {
                int r = idx >> 5, c = idx & 31;      // r = m, c = k
                if (m0 + r < M) fa[it] = *(const float4*)(A + (long)(m0 + r) * lda + k0 + c);
            }
            // B
            fb[it] = make_float4(0.f, 0.f, 0.f, 0.f);
            if constexpr (BNT) {
                int r = idx >> 5, c = idx & 31;      // r = n, c = k
                if (n0 + r < N) fb[it] = *(const float4*)(Bp + (long)(n0 + r) * ldb + k0 + c);
            } else {
                int r = idx >> 6, c = idx & 63;      // r = k, c = n
                if (n0 + c < N) fb[it] = *(const float4*)(Bp + (long)(k0 + r) * ldb + n0 + c);
            }
        }
    };
    auto stage = [&](int buf) {
#pragma unroll
        for (int it = 0; it < 2; it++) {
            int idx = tid * 4 + it * 1024;
            float av[4] = {fa[it].x, fa[it].y, fa[it].z, fa[it].w};
            float bv[4] = {fb[it].x, fb[it].y, fb[it].z, fb[it].w};
            if constexpr (ATR) {
                int r = idx >> 6, c = idx & 63;
#pragma unroll
                for (int j = 0; j < 4; j++) bsplit(av[j], Ah[buf][c + j][r], Al[buf][c + j][r]);
            } else {
                int r = idx >> 5, c = idx & 31;
#pragma unroll
                for (int j = 0; j < 4; j++) bsplit(av[j], Ah[buf][r][c + j], Al[buf][r][c + j]);
            }
            if constexpr (BNT) {
                int r = idx >> 5, c = idx & 31;
#pragma unroll
                for (int j = 0; j < 4; j++) bsplit(bv[j], Bh[buf][r][c + j], Bl[buf][r][c + j]);
            } else {
                int r = idx >> 6, c = idx & 63;
#pragma unroll
                for (int j = 0; j < 4; j++) bsplit(bv[j], Bh[buf][c + j][r], Bl[buf][c + j][r]);
            }
        }
    };

    const int nt = K / BK;
    fetch(0); stage(0);
    __syncthreads();

    for (int kt = 0; kt < nt; kt++) {
        int cur = kt & 1;
        if (kt + 1 < nt) fetch((kt + 1) * BK);
#pragma unroll
        for (int ks = 0; ks < 2; ks++) {
            int kb = ks * 16;
            int r0 = wm + g;
            unsigned ah[4], al[4];
            ah[0] = *(const unsigned*)&Ah[cur][r0][kb + t4 * 2];
            ah[1] = *(const unsigned*)&Ah[cur][r0 + 8][kb + t4 * 2];
            ah[2] = *(const unsigned*)&Ah[cur][r0][kb + t4 * 2 + 8];
            ah[3] = *(const unsigned*)&Ah[cur][r0 + 8][kb + t4 * 2 + 8];
            al[0] = *(const unsigned*)&Al[cur][r0][kb + t4 * 2];
            al[1] = *(const unsigned*)&Al[cur][r0 + 8][kb + t4 * 2];
            al[2] = *(const unsigned*)&Al[cur][r0][kb + t4 * 2 + 8];
            al[3] = *(const unsigned*)&Al[cur][r0 + 8][kb + t4 * 2 + 8];
#pragma unroll
            for (int f = 0; f < 4; f++) {
                int n = wn + f * 8 + g;
                unsigned bh[2], bl[2];
                bh[0] = *(const unsigned*)&Bh[cur][n][kb + t4 * 2];
                bh[1] = *(const unsigned*)&Bh[cur][n][kb + t4 * 2 + 8];
                bl[0] = *(const unsigned*)&Bl[cur][n][kb + t4 * 2];
                bl[1] = *(const unsigned*)&Bl[cur][n][kb + t4 * 2 + 8];
                mma16816(acc[f], ah, bh);
                mma16816(acc[f], ah, bl);
                mma16816(acc[f], al, bh);
            }
        }
        if (kt + 1 < nt) stage(cur ^ 1);
        __syncthreads();
    }

#pragma unroll
    for (int f = 0; f < 4; f++) {
        int n = n0 + wn + f * 8 + t4 * 2;
        int m = m0 + wm + g;
        float c0 = acc[f][0], c1 = acc[f][1], c2 = acc[f][2], c3 = acc[f][3];
        if (RELU) {
            c0 = fmaxf(c0, 0.f); c1 = fmaxf(c1, 0.f);
            c2 = fmaxf(c2, 0.f); c3 = fmaxf(c3, 0.f);
        }
        if (n < N) {
            if (m < M)     { C[(long)m * ldc + n] = c0;       C[(long)m * ldc + n + 1] = c1; }
            if (m + 8 < M) { C[(long)(m + 8) * ldc + n] = c2; C[(long)(m + 8) * ldc + n + 1] = c3; }
        }
    }
}

// ---------------- attention pieces ----------------
__global__ void softmax_kernel(const float* __restrict__ mask) {
    long rid = blockIdx.x;           // (b*H + h)*S + s
    int s = (int)(rid % cS);
    float* row = g_p + rid * cS;
    int t = threadIdx.x;
    __shared__ float red[256];
    float v0 = row[t] * 0.125f + mask[(long)s * cS + t];
    float v1 = row[t + 256] * 0.125f + mask[(long)s * cS + t + 256];
    float m = fmaxf(v0, v1);
    red[t] = m; __syncthreads();
    for (int o = 128; o > 0; o >>= 1) { if (t < o) red[t] = fmaxf(red[t], red[t + o]); __syncthreads(); }
    float rowmax = red[0];
    __syncthreads();
    float e0 = expf(v0 - rowmax), e1 = expf(v1 - rowmax);
    red[t] = e0 + e1; __syncthreads();
    for (int o = 128; o > 0; o >>= 1) { if (t < o) red[t] += red[t + o]; __syncthreads(); }
    float inv = 1.f / red[0];
    row[t] = e0 * inv;
    row[t + 256] = e1 * inv;
}

__global__ void vproj_kernel(const float* __restrict__ Wv) {
    int n = blockIdx.x, h = blockIdx.y, e = threadIdx.x;
    __shared__ float xs[64];
    xs[e] = g_h1[(long)n * cD + h * cDH + e];
    __syncthreads();
    int ei = g_aidx[n * cH + h];
    const float* Wp = Wv + ((long)(h * cEA + ei) * cDH) * cDH;
    float acc = 0.f;
#pragma unroll 8
    for (int d = 0; d < cDH; d++) acc += xs[d] * Wp[d * cDH + e];
    int b = n >> 9, s = n & 511;
    g_vproj[(((long)(h * cB + b) * cS) + s) * cDH + e] = acc;
}

__global__ void oproj_kernel(const float* __restrict__ Wo, const float* __restrict__ x) {
    int n = blockIdx.x, h = blockIdx.y, e = threadIdx.x;
    int b = n >> 9, s = n & 511;
    __shared__ float xs[64];
    xs[e] = g_attnout[(((long)(h * cB + b) * cS) + s) * cDH + e];
    __syncthreads();
    int ei = g_aidx[n * cH + h];
    const float* Wp = Wo + ((long)(h * cEA + ei) * cDH) * cDH;
    float acc = 0.f;
#pragma unroll 8
    for (int d = 0; d < cDH; d++) acc += xs[d] * Wp[d * cDH + e];
    g_x1[(long)n * cD + h * cDH + e] = x[(long)n * cD + h * cDH + e] + acc;
}

// ---------------- MoE FFN pieces ----------------
__global__ void gateff_kernel(const float* __restrict__ gate_w) {
    int n = blockIdx.x;
    int w = threadIdx.x >> 5, lane = threadIdx.x & 31;
    float acc = 0.f;
    for (int d = lane; d < cD; d += 32)
        acc += g_h2[(long)n * cD + d] * gate_w[(long)d * cEF + w];
#pragma unroll
    for (int o = 16; o > 0; o >>= 1) acc += __shfl_down_sync(0xffffffffu, acc, o);
    if (lane == 0) g_gl[n * cEF + w] = acc;
}

__global__ void topk_kernel() {
    int n = blockIdx.x * blockDim.x + threadIdx.x;
    if (n >= cN) return;
    float v[cEF];
#pragma unroll
    for (int j = 0; j < cEF; j++) v[j] = g_gl[n * cEF + j];
    int i1 = 0; float b1 = v[0];
#pragma unroll
    for (int j = 1; j < cEF; j++) if (v[j] > b1) { b1 = v[j]; i1 = j; }
    int i2 = -1; float b2 = -1e30f;
#pragma unroll
    for (int j = 0; j < cEF; j++) if (j != i1 && v[j] > b2) { b2 = v[j]; i2 = j; }
    float e = expf(b2 - b1);
    float inv = 1.f / (1.f + e);
    g_top_e[2 * n] = i1; g_top_e[2 * n + 1] = i2;
    g_top_p[2 * n] = inv; g_top_p[2 * n + 1] = e * inv;
}

__global__ void routeff_kernel(float* __restrict__ out, int out_size) {
    __shared__ int eids[cN * 2];
    __shared__ int spos[cN * 2];
    __shared__ float scnt[cEF], simp[cEF];
    int t = threadIdx.x;
    int warp = t >> 5, lane = t & 31;
    for (int i = t; i < cN * 2; i += 256) eids[i] = g_top_e[i];
    if (t < cEF) { scnt[t] = 0.f; simp[t] = 0.f; }
    __syncthreads();
    // warp-parallel per-expert sequential-position scan (token-major order preserved)
    if (warp < cEF) {
        int e = warp;
        int running = 0;
        for (int base = 0; base < cN * 2; base += 32) {
            int i = base + lane;
            bool match = (eids[i] == e);
            unsigned mk = __ballot_sync(0xffffffffu, match);
            if (match) spos[i] = running + __popc(mk & ((1u << lane) - 1u));
            running += __popc(mk);
        }
    }
    __syncthreads();
    for (int n = t; n < cN; n += 256) {
        float p0 = g_top_p[2 * n], p1 = g_top_p[2 * n + 1];
        int pos0 = spos[2 * n], pos1 = spos[2 * n + 1];
        float q0 = (pos0 < cCAP) ? p0 : 0.f;
        float q1 = (pos1 < cCAP) ? p1 : 0.f;
        float inv = 1.f / (q0 + q1 + 1e-9f);
        float w0 = q0 * inv, w1 = q1 * inv;
        g_w[2 * n] = w0; g_w[2 * n + 1] = w1;
        g_pos[2 * n] = pos0; g_pos[2 * n + 1] = pos1;
        if (w0 > 0.f) { atomicAdd(&scnt[eids[2 * n]], 1.f); atomicAdd(&simp[eids[2 * n]], w0); }
        if (w1 > 0.f) { atomicAdd(&scnt[eids[2 * n + 1]], 1.f); atomicAdd(&simp[eids[2 * n + 1]], w1); }
    }
    __syncthreads();
    if (t == 0 && out_size > cN * cD) {
        float cs = 0.f, is = 0.f;
        for (int e = 0; e < cEF; e++) { cs += scnt[e]; is += simp[e]; }
        float aux2 = 0.f;
        for (int e = 0; e < cEF; e++)
            aux2 += (scnt[e] / (cs + 1e-9f)) * (simp[e] / (is + 1e-9f));
        aux2 *= cEF;
        float ema[cH * cEA], es = 0.f;
        for (int i = 0; i < cH * cEA; i++) { ema[i] = 0.01f * g_hard[i] / (float)cN; es += ema[i]; }
        float aux1 = 0.f;
        for (int i = 0; i < cH * cEA; i++) { float pr = ema[i] / (es + 1e-9f); aux1 += pr * pr; }
        aux1 *= (float)(cEA * cH);
        out[cN * cD] = aux1 + aux2;
    }
}

__global__ void dispatch_kernel() {
    int a = blockIdx.x;
    int pos = g_pos[a];
    if (pos >= cCAP) return;
    int e = g_top_e[a];
    int n = a >> 1;
    float4* dst = (float4*)(g_buf + ((long)e * cCAP + pos) * cD);
    const float4* src = (const float4*)(g_h2 + (long)n * cD);
    for (int i = threadIdx.x; i < cD / 4; i += 192) dst[i] = src[i];
}

__global__ void combine_kernel(float* __restrict__ out) {
    int n = blockIdx.x;
    int e0 = g_top_e[2 * n], p0 = g_pos[2 * n];
    int e1 = g_top_e[2 * n + 1], p1 = g_pos[2 * n + 1];
    float w0 = g_w[2 * n], w1 = g_w[2 * n + 1];
    const float* y0 = g_ybuf + ((long)e0 * cCAP + (p0 < cCAP ? p0 : 0)) * cD;
    const float* y1 = g_ybuf + ((long)e1 * cCAP + (p1 < cCAP ? p1 : 0)) * cD;
    bool k0 = w0 > 0.f, k1 = w1 > 0.f;
    for (int i = threadIdx.x; i < cD; i += 256) {
        float v = g_x1[(long)n * cD + i];
        if (k0) v += w0 * y0[i];
        if (k1) v += w1 * y1[i];
        out[(long)n * cD + i] = v;
    }
}

// ---------------- launch ----------------
extern "C" void kernel_launch(void* const* d_in, const int* in_sizes, int n_in,
                              void* d_out, int out_size) {
    const float* x        = (const float*)d_in[0];
    const float* mask     = (const float*)d_in[1];
    const float* ln1_g    = (const float*)d_in[2];
    const float* ln1_b    = (const float*)d_in[3];
    const float* ln2_g    = (const float*)d_in[4];
    const float* ln2_b    = (const float*)d_in[5];
    const float* W_q      = (const float*)d_in[6];
    const float* W_k      = (const float*)d_in[7];
    const float* W_v      = (const float*)d_in[8];
    const float* W_o      = (const float*)d_in[9];
    const float* router_w = (const float*)d_in[10];
    const float* gate_w   = (const float*)d_in[11];
    const float* W1       = (const float*)d_in[12];
    const float* W2       = (const float*)d_in[13];
    float* out = (float*)d_out;

    static float *p_h1, *p_qk, *p_p, *p_vproj, *p_attnout,
                 *p_x1, *p_h2, *p_buf, *p_hmid, *p_ybuf;
    static bool init = false;
    if (!init) {
        cudaGetSymbolAddress((void**)&p_h1, g_h1);
        cudaGetSymbolAddress((void**)&p_qk, g_qk);
        cudaGetSymbolAddress((void**)&p_p, g_p);
        cudaGetSymbolAddress((void**)&p_vproj, g_vproj);
        cudaGetSymbolAddress((void**)&p_attnout, g_attnout);
        cudaGetSymbolAddress((void**)&p_x1, g_x1);
        cudaGetSymbolAddress((void**)&p_h2, g_h2);
        cudaGetSymbolAddress((void**)&p_buf, g_buf);
        cudaGetSymbolAddress((void**)&p_hmid, g_hmid);
        cudaGetSymbolAddress((void**)&p_ybuf, g_ybuf);
        init = true;
    }

    zero_kernel<<<1, 64>>>();
    ln_kernel<<<cN, 256>>>(x, ln1_g, ln1_b, p_h1);

    // Fused Q+K projection on tensor cores: z=0 -> W_q, z=1 -> W_k
    hgemm<false, false, false><<<dim3(cD / 64, cN / 64, 2), 256>>>(
        p_h1, W_q, W_k, p_qk, cN, cD, cD, cD, cD, cD,
        1, 0, 0, 0, 0, (long)cN * cD, 0);

    // Fused router projection + argmax + hard counts (fp32-exact decisions)
    router_kernel<<<cN, 256>>>(router_w);

    // scores = Q K^T on tensor cores (batched over b,h via zdiv)
    hgemm<false, true, false><<<dim3(cS / 64, cS / 64, cB * cH), 256>>>(
        p_qk, p_qk + (long)cN * cD, nullptr, p_p, cS, cS, cDH, cD, cD, cS,
        cH, (long)cS * cD, cDH, (long)cS * cD, cDH, (long)cH * cS * cS, (long)cS * cS);

    softmax_kernel<<<cB * cH * cS, 256>>>(mask);
    vproj_kernel<<<dim3(cN, cH), 64>>>(W_v);

    // attn_out = P^T V on tensor cores (ATR: A given as K x M row-major)
    hgemm<false, false, true><<<dim3(1, cS / 64, cB * cH), 256>>>(
        p_p, p_vproj, nullptr, p_attnout, cS, cDH, cS, cS, cDH, cDH,
        cH, (long)cH * cS * cS, (long)cS * cS,
        (long)cS * cDH, (long)cB * cS * cDH, (long)cS * cDH, (long)cB * cS * cDH);

    oproj_kernel<<<dim3(cN, cH), 64>>>(W_o, x);
    ln_kernel<<<cN, 256>>>(p_x1, ln2_g, ln2_b, p_h2);

    gateff_kernel<<<cN, 256>>>(gate_w);       // exact fp32 (top-k decisions)
    topk_kernel<<<cN / 128, 128>>>();
    routeff_kernel<<<1, 256>>>(out, out_size);
    dispatch_kernel<<<cN * 2, 192>>>();

    // FFN expert GEMMs on tensor cores (z = expert)
    hgemm<true, false, false><<<dim3(cDFF / 64, (cCAP + 63) / 64, cEF), 256>>>(
        p_buf, W1, nullptr, p_hmid, cCAP, cDFF, cD, cD, cDFF, cDFF,
        1, (long)cCAP * cD, 0, (long)cD * cDFF, 0, (long)cCAP * cDFF, 0);
    hgemm<false, false, false><<<dim3(cD / 64, (cCAP + 63) / 64, cEF), 256>>>(
        p_hmid, W2, nullptr, p_ybuf, cCAP, cD, cDFF, cDFF, cD, cD,
        1, (long)cCAP * cDFF, 0, (long)cDFF * cD, 0, (long)cCAP * cD, 0);

    combine_kernel<<<cN, 256>>>(out);
}

// round 17
// speedup vs baseline: 1.6234x; 1.0022x over previous
#include <cuda_runtime.h>
#include <cuda_bf16.h>
#include <math.h>

// ---------------- problem constants ----------------
static constexpr int cB = 2, cS = 512, cD = 768, cH = 12, cDH = 64;
static constexpr int cEA = 4, cEF = 8, cDFF = 3072, cN = 1024, cCAP = 160;

// ---------------- scratch (device globals) ----------
__device__ float g_h1[cN * cD];
__device__ float g_qk[2 * cN * cD];                       // [0]=Q, [1]=K
__device__ float g_p[(size_t)cB * cH * cS * cS];          // scores -> probs
__device__ int   g_aidx[cN * cH];
__device__ float g_hard[cH * cEA];
__device__ float g_vproj[cH * cB * cS * cDH];             // (h,b,s,d)
__device__ float g_attnout[cH * cB * cS * cDH];           // (h,b,t,d)
__device__ float g_x1[cN * cD];
__device__ float g_h2[cN * cD];
__device__ float g_gl[cN * cEF];
__device__ int   g_top_e[cN * 2];
__device__ float g_top_p[cN * 2];
__device__ int   g_pos[cN * 2];
__device__ float g_w[cN * 2];
__device__ float g_buf[cEF * cCAP * cD];
__device__ float g_hmid[(size_t)cEF * cCAP * cDFF];
__device__ float g_ybuf[cEF * cCAP * cD];

// ---------------- small kernels ----------------
__global__ void zero_kernel() {
    int t = threadIdx.x;
    if (t < cH * cEA) g_hard[t] = 0.f;
}

__global__ void ln_kernel(const float* __restrict__ in, const float* __restrict__ gam,
                          const float* __restrict__ bet, float* __restrict__ out) {
    int row = blockIdx.x;
    const float* r = in + (size_t)row * cD;
    __shared__ float red[256];
    int t = threadIdx.x;
    float s = 0.f;
    for (int i = t; i < cD; i += 256) s += r[i];
    red[t] = s; __syncthreads();
    for (int o = 128; o > 0; o >>= 1) { if (t < o) red[t] += red[t + o]; __syncthreads(); }
    float mu = red[0] / cD;
    __syncthreads();
    float s2 = 0.f;
    for (int i = t; i < cD; i += 256) { float d = r[i] - mu; s2 += d * d; }
    red[t] = s2; __syncthreads();
    for (int o = 128; o > 0; o >>= 1) { if (t < o) red[t] += red[t + o]; __syncthreads(); }
    float inv = rsqrtf(red[0] / cD + 1e-5f);
    for (int i = t; i < cD; i += 256)
        out[(size_t)row * cD + i] = (r[i] - mu) * inv * gam[i] + bet[i];
}

// ---------------- fused router: projection + per-head argmax + hard counts --
__global__ __launch_bounds__(256) void router_kernel(const float* __restrict__ router_w) {
    constexpr int NO = cH * cEA;   // 48 outputs
    constexpr int CH = 128;        // d-chunk size
    __shared__ float xs[cD];
    __shared__ float Ws[CH][NO + 1];   // pad -> conflict-free strided reads
    __shared__ float gates[NO];
    int n = blockIdx.x, t = threadIdx.x;
    int warp = t >> 5, lane = t & 31;
    for (int i = t; i < cD; i += 256) xs[i] = g_h1[(long)n * cD + i];
    // incremental (d,o) indexing: avoids div/mod in the hot staging loop
    const int d_start = t / NO, o_start = t % NO;   // computed once
    float acc[6] = {};                 // outputs o = warp + 8*j
    for (int c0 = 0; c0 < cD; c0 += CH) {
        __syncthreads();
        {
            int d = d_start, o = o_start;
            const float* wp = router_w + (long)c0 * NO;
#pragma unroll
            for (int it = 0; it < CH * NO / 256; it++) {
                Ws[d][o] = wp[d * NO + o];
                o += 16;               // 256 = 5*48 + 16
                d += 5;
                if (o >= NO) { o -= NO; d += 1; }
            }
        }
        __syncthreads();
#pragma unroll
        for (int j = 0; j < 6; j++) {
            int o = warp + 8 * j;
            float a = 0.f;
#pragma unroll 4
            for (int dd = lane; dd < CH; dd += 32)
                a += xs[c0 + dd] * Ws[dd][o];
            acc[j] += a;
        }
    }
#pragma unroll
    for (int j = 0; j < 6; j++) {
        float a = acc[j];
#pragma unroll
        for (int off = 16; off > 0; off >>= 1) a += __shfl_down_sync(0xffffffffu, a, off);
        if (lane == 0) gates[warp + 8 * j] = a;
    }
    __syncthreads();
    if (t < cH) {
        const float* g4 = gates + t * cEA;
        int bi = 0; float bv = g4[0];
#pragma unroll
        for (int ea = 1; ea < cEA; ea++) if (g4[ea] > bv) { bv = g4[ea]; bi = ea; }
        g_aidx[n * cH + t] = bi;
        atomicAdd(&g_hard[t * cEA + bi], 1.f);
    }
}

// ---------------- bf16 3-term split tensor-core GEMM (double-buffered) -----
// fp32 in/out, computed as (Ah+Al)(Bh+Bl) dropping only Al*Bl (~2^-18 rel).
// ATR=false: A is (MxK) row-major.   ATR=true: A is (KxM) row-major (C = A^T B).
// BNT=false: B is (KxN) row-major.   BNT=true: B is (NxK) row-major (C = A B^T).
// If B2 != nullptr and zb>0, B2 is used instead of B.
__device__ __forceinline__ void mma16816(float* d, const unsigned* a, const unsigned* b) {
    asm volatile(
        "mma.sync.aligned.m16n8k16.row.col.f32.bf16.bf16.f32 "
        "{%0,%1,%2,%3}, {%4,%5,%6,%7}, {%8,%9}, {%0,%1,%2,%3};"
        : "+f"(d[0]), "+f"(d[1]), "+f"(d[2]), "+f"(d[3])
        : "r"(a[0]), "r"(a[1]), "r"(a[2]), "r"(a[3]), "r"(b[0]), "r"(b[1]));
}

__device__ __forceinline__ void bsplit(float x, __nv_bfloat16& h, __nv_bfloat16& l) {
    h = __float2bfloat16(x);
    l = __float2bfloat16(x - __bfloat162float(h));
}

template<bool RELU, bool BNT, bool ATR>
__global__ __launch_bounds__(256) void hgemm(
    const float* __restrict__ A, const float* __restrict__ B,
    const float* __restrict__ B2, float* __restrict__ C,
    int M, int N, int K, int lda, int ldb, int ldc,
    int zdiv, long sA1, long sA2, long sB1, long sB2, long sC1, long sC2)
{
    constexpr int BK = 32;
    int zb = blockIdx.z / zdiv, zi = blockIdx.z % zdiv;
    A += (long)zb * sA1 + (long)zi * sA2;
    const float* Bp = (B2 != nullptr && zb > 0) ? B2 : B;
    Bp += (long)zb * sB1 + (long)zi * sB2;
    C += (long)zb * sC1 + (long)zi * sC2;

    __shared__ __nv_bfloat16 Ah[2][64][BK + 8], Al[2][64][BK + 8];
    __shared__ __nv_bfloat16 Bh[2][64][BK + 8], Bl[2][64][BK + 8];

    const int tid = threadIdx.x;
    const int m0 = blockIdx.y * 64, n0 = blockIdx.x * 64;
    const int wid = tid >> 5, lane = tid & 31;
    const int wm = (wid & 3) * 16, wn = (wid >> 2) * 32;
    const int g = lane >> 2, t4 = lane & 3;

    float acc[4][4] = {};
    float4 fa[2], fb[2];

    auto fetch = [&](int k0) {
#pragma unroll
        for (int it = 0; it < 2; it++) {
            int idx = tid * 4 + it * 1024;
            // A
            fa[it] = make_float4(0.f, 0.f, 0.f, 0.f);
            if constexpr (ATR) {
                int r = idx >> 6, c = idx & 63;      // r = k (0..31), c = m
                if (m0 + c < M) fa[it] = *(const float4*)(A + (long)(k0 + r) * lda + m0 + c);
            } else {
                int r = idx >> 5, c = idx & 31;      // r = m, c = k
                if (m0 + r < M) fa[it] = *(const float4*)(A + (long)(m0 + r) * lda + k0 + c);
            }
            // B
            fb[it] = make_float4(0.f, 0.f, 0.f, 0.f);
            if constexpr (BNT) {
                int r = idx >> 5, c = idx & 31;      // r = n, c = k
                if (n0 + r < N) fb[it] = *(const float4*)(Bp + (long)(n0 + r) * ldb + k0 + c);
            } else {
                int r = idx >> 6, c = idx & 63;      // r = k, c = n
                if (n0 + c < N) fb[it] = *(const float4*)(Bp + (long)(k0 + r) * ldb + n0 + c);
            }
        }
    };
    auto stage = [&](int buf) {
#pragma unroll
        for (int it = 0; it < 2; it++) {
            int idx = tid * 4 + it * 1024;
            float av[4] = {fa[it].x, fa[it].y, fa[it].z, fa[it].w};
            float bv[4] = {fb[it].x, fb[it].y, fb[it].z, fb[it].w};
            if constexpr (ATR) {
                int r = idx >> 6, c = idx & 63;
#pragma unroll
                for (int j = 0; j < 4; j++) bsplit(av[j], Ah[buf][c + j][r], Al[buf][c + j][r]);
            } else {
                int r = idx >> 5, c = idx & 31;
#pragma unroll
                for (int j = 0; j < 4; j++) bsplit(av[j], Ah[buf][r][c + j], Al[buf][r][c + j]);
            }
            if constexpr (BNT) {
                int r = idx >> 5, c = idx & 31;
#pragma unroll
                for (int j = 0; j < 4; j++) bsplit(bv[j], Bh[buf][r][c + j], Bl[buf][r][c + j]);
            } else {
                int r = idx >> 6, c = idx & 63;
#pragma unroll
                for (int j = 0; j < 4; j++) bsplit(bv[j], Bh[buf][c + j][r], Bl[buf][c + j][r]);
            }
        }
    };

    const int nt = K / BK;
    fetch(0); stage(0);
    __syncthreads();

    for (int kt = 0; kt < nt; kt++) {
        int cur = kt & 1;
        if (kt + 1 < nt) fetch((kt + 1) * BK);
#pragma unroll
        for (int ks = 0; ks < 2; ks++) {
            int kb = ks * 16;
            int r0 = wm + g;
            unsigned ah[4], al[4];
            ah[0] = *(const unsigned*)&Ah[cur][r0][kb + t4 * 2];
            ah[1] = *(const unsigned*)&Ah[cur][r0 + 8][kb + t4 * 2];
            ah[2] = *(const unsigned*)&Ah[cur][r0][kb + t4 * 2 + 8];
            ah[3] = *(const unsigned*)&Ah[cur][r0 + 8][kb + t4 * 2 + 8];
            al[0] = *(const unsigned*)&Al[cur][r0][kb + t4 * 2];
            al[1] = *(const unsigned*)&Al[cur][r0 + 8][kb + t4 * 2];
            al[2] = *(const unsigned*)&Al[cur][r0][kb + t4 * 2 + 8];
            al[3] = *(const unsigned*)&Al[cur][r0 + 8][kb + t4 * 2 + 8];
#pragma unroll
            for (int f = 0; f < 4; f++) {
                int n = wn + f * 8 + g;
                unsigned bh[2], bl[2];
                bh[0] = *(const unsigned*)&Bh[cur][n][kb + t4 * 2];
                bh[1] = *(const unsigned*)&Bh[cur][n][kb + t4 * 2 + 8];
                bl[0] = *(const unsigned*)&Bl[cur][n][kb + t4 * 2];
                bl[1] = *(const unsigned*)&Bl[cur][n][kb + t4 * 2 + 8];
                mma16816(acc[f], ah, bh);
                mma16816(acc[f], ah, bl);
                mma16816(acc[f], al, bh);
            }
        }
        if (kt + 1 < nt) stage(cur ^ 1);
        __syncthreads();
    }

#pragma unroll
    for (int f = 0; f < 4; f++) {
        int n = n0 + wn + f * 8 + t4 * 2;
        int m = m0 + wm + g;
        float c0 = acc[f][0], c1 = acc[f][1], c2 = acc[f][2], c3 = acc[f][3];
        if (RELU) {
            c0 = fmaxf(c0, 0.f); c1 = fmaxf(c1, 0.f);
            c2 = fmaxf(c2, 0.f); c3 = fmaxf(c3, 0.f);
        }
        if (n < N) {
            if (m < M)     { C[(long)m * ldc + n] = c0;       C[(long)m * ldc + n + 1] = c1; }
            if (m + 8 < M) { C[(long)(m + 8) * ldc + n] = c2; C[(long)(m + 8) * ldc + n + 1] = c3; }
        }
    }
}

// ---------------- attention pieces ----------------
__global__ void softmax_kernel(const float* __restrict__ mask) {
    long rid = blockIdx.x;           // (b*H + h)*S + s
    int s = (int)(rid % cS);
    float* row = g_p + rid * cS;
    int t = threadIdx.x;
    __shared__ float red[256];
    float v0 = row[t] * 0.125f + mask[(long)s * cS + t];
    float v1 = row[t + 256] * 0.125f + mask[(long)s * cS + t + 256];
    float m = fmaxf(v0, v1);
    red[t] = m; __syncthreads();
    for (int o = 128; o > 0; o >>= 1) { if (t < o) red[t] = fmaxf(red[t], red[t + o]); __syncthreads(); }
    float rowmax = red[0];
    __syncthreads();
    float e0 = expf(v0 - rowmax), e1 = expf(v1 - rowmax);
    red[t] = e0 + e1; __syncthreads();
    for (int o = 128; o > 0; o >>= 1) { if (t < o) red[t] += red[t + o]; __syncthreads(); }
    float inv = 1.f / red[0];
    row[t] = e0 * inv;
    row[t + 256] = e1 * inv;
}

__global__ void vproj_kernel(const float* __restrict__ Wv) {
    int n = blockIdx.x, h = blockIdx.y, e = threadIdx.x;
    __shared__ float xs[64];
    xs[e] = g_h1[(long)n * cD + h * cDH + e];
    __syncthreads();
    int ei = g_aidx[n * cH + h];
    const float* Wp = Wv + ((long)(h * cEA + ei) * cDH) * cDH;
    float acc = 0.f;
#pragma unroll 8
    for (int d = 0; d < cDH; d++) acc += xs[d] * Wp[d * cDH + e];
    int b = n >> 9, s = n & 511;
    g_vproj[(((long)(h * cB + b) * cS) + s) * cDH + e] = acc;
}

__global__ void oproj_kernel(const float* __restrict__ Wo, const float* __restrict__ x) {
    int n = blockIdx.x, h = blockIdx.y, e = threadIdx.x;
    int b = n >> 9, s = n & 511;
    __shared__ float xs[64];
    xs[e] = g_attnout[(((long)(h * cB + b) * cS) + s) * cDH + e];
    __syncthreads();
    int ei = g_aidx[n * cH + h];
    const float* Wp = Wo + ((long)(h * cEA + ei) * cDH) * cDH;
    float acc = 0.f;
#pragma unroll 8
    for (int d = 0; d < cDH; d++) acc += xs[d] * Wp[d * cDH + e];
    g_x1[(long)n * cD + h * cDH + e] = x[(long)n * cD + h * cDH + e] + acc;
}

// ---------------- MoE FFN pieces ----------------
__global__ void gateff_kernel(const float* __restrict__ gate_w) {
    int n = blockIdx.x;
    int w = threadIdx.x >> 5, lane = threadIdx.x & 31;
    float acc = 0.f;
    for (int d = lane; d < cD; d += 32)
        acc += g_h2[(long)n * cD + d] * gate_w[(long)d * cEF + w];
#pragma unroll
    for (int o = 16; o > 0; o >>= 1) acc += __shfl_down_sync(0xffffffffu, acc, o);
    if (lane == 0) g_gl[n * cEF + w] = acc;
}

__global__ void topk_kernel() {
    int n = blockIdx.x * blockDim.x + threadIdx.x;
    if (n >= cN) return;
    float v[cEF];
#pragma unroll
    for (int j = 0; j < cEF; j++) v[j] = g_gl[n * cEF + j];
    int i1 = 0; float b1 = v[0];
#pragma unroll
    for (int j = 1; j < cEF; j++) if (v[j] > b1) { b1 = v[j]; i1 = j; }
    int i2 = -1; float b2 = -1e30f;
#pragma unroll
    for (int j = 0; j < cEF; j++) if (j != i1 && v[j] > b2) { b2 = v[j]; i2 = j; }
    float e = expf(b2 - b1);
    float inv = 1.f / (1.f + e);
    g_top_e[2 * n] = i1; g_top_e[2 * n + 1] = i2;
    g_top_p[2 * n] = inv; g_top_p[2 * n + 1] = e * inv;
}

__global__ void routeff_kernel(float* __restrict__ out, int out_size) {
    __shared__ int eids[cN * 2];
    __shared__ int spos[cN * 2];
    __shared__ float scnt[cEF], simp[cEF];
    int t = threadIdx.x;
    int warp = t >> 5, lane = t & 31;
    for (int i = t; i < cN * 2; i += 256) eids[i] = g_top_e[i];
    if (t < cEF) { scnt[t] = 0.f; simp[t] = 0.f; }
    __syncthreads();
    // warp-parallel per-expert sequential-position scan (token-major order preserved)
    if (warp < cEF) {
        int e = warp;
        int running = 0;
        for (int base = 0; base < cN * 2; base += 32) {
            int i = base + lane;
            bool match = (eids[i] == e);
            unsigned mk = __ballot_sync(0xffffffffu, match);
            if (match) spos[i] = running + __popc(mk & ((1u << lane) - 1u));
            running += __popc(mk);
        }
    }
    __syncthreads();
    for (int n = t; n < cN; n += 256) {
        float p0 = g_top_p[2 * n], p1 = g_top_p[2 * n + 1];
        int pos0 = spos[2 * n], pos1 = spos[2 * n + 1];
        float q0 = (pos0 < cCAP) ? p0 : 0.f;
        float q1 = (pos1 < cCAP) ? p1 : 0.f;
        float inv = 1.f / (q0 + q1 + 1e-9f);
        float w0 = q0 * inv, w1 = q1 * inv;
        g_w[2 * n] = w0; g_w[2 * n + 1] = w1;
        g_pos[2 * n] = pos0; g_pos[2 * n + 1] = pos1;
        if (w0 > 0.f) { atomicAdd(&scnt[eids[2 * n]], 1.f); atomicAdd(&simp[eids[2 * n]], w0); }
        if (w1 > 0.f) { atomicAdd(&scnt[eids[2 * n + 1]], 1.f); atomicAdd(&simp[eids[2 * n + 1]], w1); }
    }
    __syncthreads();
    if (t == 0 && out_size > cN * cD) {
        float cs = 0.f, is = 0.f;
        for (int e = 0; e < cEF; e++) { cs += scnt[e]; is += simp[e]; }
        float aux2 = 0.f;
        for (int e = 0; e < cEF; e++)
            aux2 += (scnt[e] / (cs + 1e-9f)) * (simp[e] / (is + 1e-9f));
        aux2 *= cEF;
        float ema[cH * cEA], es = 0.f;
        for (int i = 0; i < cH * cEA; i++) { ema[i] = 0.01f * g_hard[i] / (float)cN; es += ema[i]; }
        float aux1 = 0.f;
        for (int i = 0; i < cH * cEA; i++) { float pr = ema[i] / (es + 1e-9f); aux1 += pr * pr; }
        aux1 *= (float)(cEA * cH);
        out[cN * cD] = aux1 + aux2;
    }
}

__global__ void dispatch_kernel() {
    int a = blockIdx.x;
    int pos = g_pos[a];
    if (pos >= cCAP) return;
    int e = g_top_e[a];
    int n = a >> 1;
    float4* dst = (float4*)(g_buf + ((long)e * cCAP + pos) * cD);
    const float4* src = (const float4*)(g_h2 + (long)n * cD);
    for (int i = threadIdx.x; i < cD / 4; i += 192) dst[i] = src[i];
}

__global__ void combine_kernel(float* __restrict__ out) {
    int n = blockIdx.x;
    int e0 = g_top_e[2 * n], p0 = g_pos[2 * n];
    int e1 = g_top_e[2 * n + 1], p1 = g_pos[2 * n + 1];
    float w0 = g_w[2 * n], w1 = g_w[2 * n + 1];
    const float* y0 = g_ybuf + ((long)e0 * cCAP + (p0 < cCAP ? p0 : 0)) * cD;
    const float* y1 = g_ybuf + ((long)e1 * cCAP + (p1 < cCAP ? p1 : 0)) * cD;
    bool k0 = w0 > 0.f, k1 = w1 > 0.f;
    for (int i = threadIdx.x; i < cD; i += 256) {
        float v = g_x1[(long)n * cD + i];
        if (k0) v += w0 * y0[i];
        if (k1) v += w1 * y1[i];
        out[(long)n * cD + i] = v;
    }
}

// ---------------- launch ----------------
extern "C" void kernel_launch(void* const* d_in, const int* in_sizes, int n_in,
                              void* d_out, int out_size) {
    const float* x        = (const float*)d_in[0];
    const float* mask     = (const float*)d_in[1];
    const float* ln1_g    = (const float*)d_in[2];
    const float* ln1_b    = (const float*)d_in[3];
    const float* ln2_g    = (const float*)d_in[4];
    const float* ln2_b    = (const float*)d_in[5];
    const float* W_q      = (const float*)d_in[6];
    const float* W_k      = (const float*)d_in[7];
    const float* W_v      = (const float*)d_in[8];
    const float* W_o      = (const float*)d_in[9];
    const float* router_w = (const float*)d_in[10];
    const float* gate_w   = (const float*)d_in[11];
    const float* W1       = (const float*)d_in[12];
    const float* W2       = (const float*)d_in[13];
    float* out = (float*)d_out;

    static float *p_h1, *p_qk, *p_p, *p_vproj, *p_attnout,
                 *p_x1, *p_h2, *p_buf, *p_hmid, *p_ybuf;
    static bool init = false;
    if (!init) {
        cudaGetSymbolAddress((void**)&p_h1, g_h1);
        cudaGetSymbolAddress((void**)&p_qk, g_qk);
        cudaGetSymbolAddress((void**)&p_p, g_p);
        cudaGetSymbolAddress((void**)&p_vproj, g_vproj);
        cudaGetSymbolAddress((void**)&p_attnout, g_attnout);
        cudaGetSymbolAddress((void**)&p_x1, g_x1);
        cudaGetSymbolAddress((void**)&p_h2, g_h2);
        cudaGetSymbolAddress((void**)&p_buf, g_buf);
        cudaGetSymbolAddress((void**)&p_hmid, g_hmid);
        cudaGetSymbolAddress((void**)&p_ybuf, g_ybuf);
        init = true;
    }

    zero_kernel<<<1, 64>>>();
    ln_kernel<<<cN, 256>>>(x, ln1_g, ln1_b, p_h1);

    // Fused Q+K projection on tensor cores: z=0 -> W_q, z=1 -> W_k
    hgemm<false, false, false><<<dim3(cD / 64, cN / 64, 2), 256>>>(
        p_h1, W_q, W_k, p_qk, cN, cD, cD, cD, cD, cD,
        1, 0, 0, 0, 0, (long)cN * cD, 0);

    // Fused router projection + argmax + hard counts (fp32-exact decisions)
    router_kernel<<<cN, 256>>>(router_w);

    // scores = Q K^T on tensor cores (batched over b,h via zdiv)
    hgemm<false, true, false><<<dim3(cS / 64, cS / 64, cB * cH), 256>>>(
        p_qk, p_qk + (long)cN * cD, nullptr, p_p, cS, cS, cDH, cD, cD, cS,
        cH, (long)cS * cD, cDH, (long)cS * cD, cDH, (long)cH * cS * cS, (long)cS * cS);

    softmax_kernel<<<cB * cH * cS, 256>>>(mask);
    vproj_kernel<<<dim3(cN, cH), 64>>>(W_v);

    // attn_out = P^T V on tensor cores (ATR: A given as K x M row-major)
    hgemm<false, false, true><<<dim3(1, cS / 64, cB * cH), 256>>>(
        p_p, p_vproj, nullptr, p_attnout, cS, cDH, cS, cS, cDH, cDH,
        cH, (long)cH * cS * cS, (long)cS * cS,
        (long)cS * cDH, (long)cB * cS * cDH, (long)cS * cDH, (long)cB * cS * cDH);

    oproj_kernel<<<dim3(cN, cH), 64>>>(W_o, x);
    ln_kernel<<<cN, 256>>>(p_x1, ln2_g, ln2_b, p_h2);

    gateff_kernel<<<cN, 256>>>(gate_w);       // exact fp32 (top-k decisions)
    topk_kernel<<<cN / 128, 128>>>();
    routeff_kernel<<<1, 256>>>(out, out_size);
    dispatch_kernel<<<cN * 2, 192>>>();

    // FFN expert GEMMs on tensor cores (z = expert)
    hgemm<true, false, false><<<dim3(cDFF / 64, (cCAP + 63) / 64, cEF), 256>>>(
        p_buf, W1, nullptr, p_hmid, cCAP, cDFF, cD, cD, cDFF, cDFF,
        1, (long)cCAP * cD, 0, (long)cD * cDFF, 0, (long)cCAP * cDFF, 0);
    hgemm<false, false, false><<<dim3(cD / 64, (cCAP + 63) / 64, cEF), 256>>>(
        p_hmid, W2, nullptr, p_ybuf, cCAP, cD, cDFF, cDFF, cD, cD,
        1, (long)cCAP * cDFF, 0, (long)cDFF * cD, 0, (long)cCAP * cD, 0);

    combine_kernel<<<cN, 256>>>(out);
}